// round 1
// baseline (speedup 1.0000x reference)
#include <cuda_runtime.h>
#include <math.h>

#define NN 50000
#define NE 800000
#define DDA 256
#define DDB 128
#define HD  256
#define EPS_BN 1e-5f
#define SLOPE_LR 0.01f

// ---------------- scratch (__device__ globals; no allocation allowed) ----------------
__device__ float g_aggr0[(size_t)NN * HD];   // aggr for edge_ab (dst = B space)
__device__ float g_aggr1[(size_t)NN * HD];   // aggr for edge_ba (dst = A space)
__device__ float g_aggr2[(size_t)NN * HD];   // aggr for edge_aa (dst = A space)
__device__ float g_hA[(size_t)NN * HD];
__device__ float g_hB[(size_t)NN * HD];
__device__ float g_preA[(size_t)NN * HD];
__device__ float g_preB[(size_t)NN * HD];
__device__ float g_cnt[3 * NN];              // ab, ba, aa in-degree counts
__device__ float g_WA1[HD * 640];
__device__ float g_WB1[HD * 384];
__device__ float g_WA2[HD * 768];
__device__ float g_WB2[HD * 512];
__device__ float g_bA1[HD], g_bB1[HD], g_bA2[HD], g_bB2[HD];
__device__ float g_stat[2 * HD];             // col sums, col sumsq
__device__ float g_sc[HD], g_sh[HD];         // BN scale/shift

// ---------------- utility kernels ----------------
__global__ void zero_kernel(float* __restrict__ p, int n4) {
    int i = blockIdx.x * blockDim.x + threadIdx.x;
    if (i < n4) reinterpret_cast<float4*>(p)[i] = make_float4(0.f, 0.f, 0.f, 0.f);
}

__global__ void count_kernel(const int* __restrict__ dst, float* __restrict__ cnt, int E) {
    int e = blockIdx.x * blockDim.x + threadIdx.x;
    if (e < E) atomicAdd(cnt + dst[e], 1.0f);
}

// D = 256 scatter-add: 4 edges per 256-thread block, 64 float4 chunks each
__global__ void scatter256_kernel(const float* __restrict__ feat,
                                  const int* __restrict__ src,
                                  const int* __restrict__ dst,
                                  float* __restrict__ out, int E) {
    int lane = threadIdx.x & 63;
    int slot = threadIdx.x >> 6;
    int e = blockIdx.x * 4 + slot;
    if (e >= E) return;
    int s = src[e];
    int d = dst[e];
    float4 v = reinterpret_cast<const float4*>(feat + (size_t)s * 256)[lane];
    float* dp = out + (size_t)d * 256 + lane * 4;
    atomicAdd(dp + 0, v.x);
    atomicAdd(dp + 1, v.y);
    atomicAdd(dp + 2, v.z);
    atomicAdd(dp + 3, v.w);
}

// D = 128 scatter-add: 8 edges per 256-thread block, 32 float4 chunks each
__global__ void scatter128_kernel(const float* __restrict__ feat,
                                  const int* __restrict__ src,
                                  const int* __restrict__ dst,
                                  float* __restrict__ out, int E) {
    int lane = threadIdx.x & 31;
    int slot = threadIdx.x >> 5;
    int e = blockIdx.x * 8 + slot;
    if (e >= E) return;
    int s = src[e];
    int d = dst[e];
    float4 v = reinterpret_cast<const float4*>(feat + (size_t)s * 128)[lane];
    float* dp = out + (size_t)d * 128 + lane * 4;
    atomicAdd(dp + 0, v.x);
    atomicAdd(dp + 1, v.y);
    atomicAdd(dp + 2, v.z);
    atomicAdd(dp + 3, v.w);
}

// aggr[n][*] *= 1 / max(cnt[n], 1)
__global__ void normalize_kernel(float* __restrict__ buf, const float* __restrict__ cnt, int D4) {
    int i = blockIdx.x * blockDim.x + threadIdx.x;
    int total = NN * D4;
    if (i >= total) return;
    int n = i / D4;
    float r = 1.0f / fmaxf(cnt[n], 1.0f);
    float4 v = reinterpret_cast<float4*>(buf)[i];
    v.x *= r; v.y *= r; v.z *= r; v.w *= r;
    reinterpret_cast<float4*>(buf)[i] = v;
}

// out[o][ocoff+j] = beta*out[...] + scale * sum_i Wupd[o][coff+i] * Ws[i][j]
__global__ void combine_w_kernel(const float* __restrict__ Wupd, int wstride, int coff,
                                 const float* __restrict__ Ws, int d,
                                 float scale, float beta,
                                 float* __restrict__ out, int ostride, int ocoff) {
    int j = blockIdx.x * 32 + (threadIdx.x & 31);
    int o = blockIdx.y * 8 + (threadIdx.x >> 5);
    if (j >= d) return;
    float acc = 0.f;
    const float* wrow = Wupd + (size_t)o * wstride + coff;
#pragma unroll 4
    for (int i = 0; i < HD; i++)
        acc = fmaf(wrow[i], Ws[(size_t)i * d + j], acc);
    float* op = out + (size_t)o * ostride + ocoff + j;
    *op = beta * (*op) + scale * acc;
}

// out[o] = beta*out[o] + scale*(bupd[o] + sum_i Wupd[o][i]*bdst[i] + Wupd[o][HD+i]*bsrc[i])
__global__ void combine_b_kernel(const float* __restrict__ Wupd, int wstride,
                                 const float* __restrict__ bsrc,
                                 const float* __restrict__ bdst,
                                 const float* __restrict__ bupd,
                                 float scale, float beta, float* __restrict__ out) {
    int o = threadIdx.x;
    float acc = bupd[o];
    const float* wrow = Wupd + (size_t)o * wstride;
#pragma unroll 4
    for (int i = 0; i < HD; i++)
        acc += wrow[i] * bdst[i] + wrow[HD + i] * bsrc[i];
    out[o] = beta * out[o] + scale * acc;
}

// C[M,256] = [A0|A1|A2] @ W^T + bias ; W is [256][Ktot] row-major; segmented K
__global__ __launch_bounds__(256) void gemm_kernel(
    const float* __restrict__ A0, int K0,
    const float* __restrict__ A1, int K1,
    const float* __restrict__ A2, int K2,
    const float* __restrict__ W, const float* __restrict__ bias,
    float* __restrict__ C, int M) {
    const int Ktot = K0 + K1 + K2;
    __shared__ float As[8][128];
    __shared__ float Bs[8][128];
    int tid = threadIdx.x;
    int m0 = blockIdx.y * 128;
    int n0 = blockIdx.x * 128;
    float acc[8][8];
#pragma unroll
    for (int i = 0; i < 8; i++)
#pragma unroll
        for (int j = 0; j < 8; j++) acc[i][j] = 0.f;

    int arow = tid >> 1;         // 0..127
    int akq = (tid & 1) * 4;     // 0 or 4
    int gm = m0 + arow;
    int gn = n0 + arow;
    int tx = tid & 15, ty = tid >> 4;

    for (int kb = 0; kb < Ktot; kb += 8) {
        const float* Ap;
        int sw, kl;
        if (kb < K0)           { Ap = A0; sw = K0; kl = kb; }
        else if (kb < K0 + K1) { Ap = A1; sw = K1; kl = kb - K0; }
        else                   { Ap = A2; sw = K2; kl = kb - K0 - K1; }

        float4 av = make_float4(0.f, 0.f, 0.f, 0.f);
        if (gm < M) av = *reinterpret_cast<const float4*>(Ap + (size_t)gm * sw + kl + akq);
        float4 bv = *reinterpret_cast<const float4*>(W + (size_t)gn * Ktot + kb + akq);

        As[akq + 0][arow] = av.x; As[akq + 1][arow] = av.y;
        As[akq + 2][arow] = av.z; As[akq + 3][arow] = av.w;
        Bs[akq + 0][arow] = bv.x; Bs[akq + 1][arow] = bv.y;
        Bs[akq + 2][arow] = bv.z; Bs[akq + 3][arow] = bv.w;
        __syncthreads();

#pragma unroll
        for (int k = 0; k < 8; k++) {
            float a[8], b[8];
#pragma unroll
            for (int i = 0; i < 8; i++) a[i] = As[k][ty * 8 + i];
#pragma unroll
            for (int j = 0; j < 8; j++) b[j] = Bs[k][tx * 8 + j];
#pragma unroll
            for (int i = 0; i < 8; i++)
#pragma unroll
                for (int j = 0; j < 8; j++) acc[i][j] = fmaf(a[i], b[j], acc[i][j]);
        }
        __syncthreads();
    }

#pragma unroll
    for (int i = 0; i < 8; i++) {
        int m = m0 + ty * 8 + i;
        if (m >= M) break;
#pragma unroll
        for (int j = 0; j < 8; j += 4) {
            int n = n0 + tx * 8 + j;
            float4 o;
            o.x = acc[i][j + 0] + bias[n + 0];
            o.y = acc[i][j + 1] + bias[n + 1];
            o.z = acc[i][j + 2] + bias[n + 2];
            o.w = acc[i][j + 3] + bias[n + 3];
            *reinterpret_cast<float4*>(C + (size_t)m * 256 + n) = o;
        }
    }
}

// column-wise sum / sumsq partials (coalesced: thread t handles column t)
__global__ void stats_kernel(const float* __restrict__ X, int M,
                             float* __restrict__ s, float* __restrict__ s2) {
    int t = threadIdx.x;
    int rows_per = (M + gridDim.x - 1) / gridDim.x;
    int r0 = blockIdx.x * rows_per;
    int r1 = min(r0 + rows_per, M);
    float a = 0.f, b = 0.f;
    for (int r = r0; r < r1; r++) {
        float v = X[(size_t)r * 256 + t];
        a += v;
        b += v * v;
    }
    atomicAdd(s + t, a);
    atomicAdd(s2 + t, b);
}

__global__ void bn_finalize_kernel(const float* __restrict__ s, const float* __restrict__ s2,
                                   const float* __restrict__ g, const float* __restrict__ bb,
                                   int M, float* __restrict__ sc, float* __restrict__ sh) {
    int t = threadIdx.x;
    float mean = s[t] / (float)M;
    float var = s2[t] / (float)M - mean * mean;
    float a = g[t] * rsqrtf(var + EPS_BN);
    sc[t] = a;
    sh[t] = bb[t] - mean * a;
}

__global__ void bn_apply_kernel(const float* __restrict__ X,
                                const float* __restrict__ sc, const float* __restrict__ sh,
                                float* __restrict__ Y, int M) {
    int i = blockIdx.x * blockDim.x + threadIdx.x;
    if (i >= M * 64) return;
    int c4 = i & 63;
    float4 a = reinterpret_cast<const float4*>(sc)[c4];
    float4 c = reinterpret_cast<const float4*>(sh)[c4];
    float4 x = reinterpret_cast<const float4*>(X)[i];
    float4 y;
    y.x = a.x * x.x + c.x; y.x = y.x > 0.f ? y.x : SLOPE_LR * y.x;
    y.y = a.y * x.y + c.y; y.y = y.y > 0.f ? y.y : SLOPE_LR * y.y;
    y.z = a.z * x.z + c.z; y.z = y.z > 0.f ? y.z : SLOPE_LR * y.z;
    y.w = a.w * x.w + c.w; y.w = y.w > 0.f ? y.w : SLOPE_LR * y.w;
    reinterpret_cast<float4*>(Y)[i] = y;
}

// ---------------- host orchestration ----------------
static inline float* sym(const void* s) {
    void* p = nullptr;
    cudaGetSymbolAddress(&p, s);
    return (float*)p;
}

extern "C" void kernel_launch(void* const* d_in, const int* in_sizes, int n_in,
                              void* d_out, int out_size) {
    (void)in_sizes; (void)n_in; (void)out_size;
    const float* x_A = (const float*)d_in[0];
    const float* x_B = (const float*)d_in[1];
    const int* e_ab = (const int*)d_in[2];
    const int* e_ba = (const int*)d_in[3];
    const int* e_aa = (const int*)d_in[4];
    const float* ab_Wsrc1 = (const float*)d_in[5];
    const float* ab_bsrc1 = (const float*)d_in[6];
    const float* ab_Wdst1 = (const float*)d_in[7];
    const float* ab_bdst1 = (const float*)d_in[8];
    const float* ab_Wupd1 = (const float*)d_in[9];
    const float* ab_bupd1 = (const float*)d_in[10];
    const float* ba_Wsrc1 = (const float*)d_in[11];
    const float* ba_bsrc1 = (const float*)d_in[12];
    const float* ba_Wdst1 = (const float*)d_in[13];
    const float* ba_bdst1 = (const float*)d_in[14];
    const float* ba_Wupd1 = (const float*)d_in[15];
    const float* ba_bupd1 = (const float*)d_in[16];
    const float* aa_Wsrc1 = (const float*)d_in[17];
    const float* aa_bsrc1 = (const float*)d_in[18];
    const float* aa_Wdst1 = (const float*)d_in[19];
    const float* aa_bdst1 = (const float*)d_in[20];
    const float* aa_Wupd1 = (const float*)d_in[21];
    const float* aa_bupd1 = (const float*)d_in[22];
    const float* Wsrc2 = (const float*)d_in[23];
    const float* bsrc2 = (const float*)d_in[24];
    const float* Wdst2 = (const float*)d_in[25];
    const float* bdst2 = (const float*)d_in[26];
    const float* Wupd2 = (const float*)d_in[27];
    const float* bupd2 = (const float*)d_in[28];
    const float* bn_g = (const float*)d_in[29];
    const float* bn_b = (const float*)d_in[30];
    float* out = (float*)d_out;

    float* aggr0 = sym(g_aggr0);
    float* aggr1 = sym(g_aggr1);
    float* aggr2 = sym(g_aggr2);
    float* hA = sym(g_hA);
    float* hB = sym(g_hB);
    float* preA = sym(g_preA);
    float* preB = sym(g_preB);
    float* cnt = sym(g_cnt);
    float* WA1 = sym(g_WA1);
    float* WB1 = sym(g_WB1);
    float* WA2 = sym(g_WA2);
    float* WB2 = sym(g_WB2);
    float* bA1 = sym(g_bA1);
    float* bB1 = sym(g_bB1);
    float* bA2 = sym(g_bA2);
    float* bB2 = sym(g_bB2);
    float* stat = sym(g_stat);
    float* sc = sym(g_sc);
    float* sh = sym(g_sh);

    float* cnt_ab = cnt;
    float* cnt_ba = cnt + NN;
    float* cnt_aa = cnt + 2 * NN;

    const int AGGR4 = NN * HD / 4;                 // 3.2M float4
    const int ZB = (AGGR4 + 255) / 256;
    dim3 cw_blk(256);

    // ---- degree counts (shared by both layers) ----
    zero_kernel<<<((3 * NN / 4) + 255) / 256, 256>>>(cnt, 3 * NN / 4);
    count_kernel<<<(NE + 255) / 256, 256>>>(e_ab + NE, cnt_ab, NE);
    count_kernel<<<(NE + 255) / 256, 256>>>(e_ba + NE, cnt_ba, NE);
    count_kernel<<<(NE + 255) / 256, 256>>>(e_aa + NE, cnt_aa, NE);

    // ---- combined weights ----
    // Layer-1 A side: [x_A(256) | aggr_ba(128) | aggr_aa(256)], Ktot=640
    combine_w_kernel<<<dim3(8, 32), cw_blk>>>(ba_Wupd1, 512, 0,   ba_Wdst1, 256, 0.5f, 0.f, WA1, 640, 0);
    combine_w_kernel<<<dim3(8, 32), cw_blk>>>(aa_Wupd1, 512, 0,   aa_Wdst1, 256, 0.5f, 1.f, WA1, 640, 0);
    combine_w_kernel<<<dim3(4, 32), cw_blk>>>(ba_Wupd1, 512, 256, ba_Wsrc1, 128, 0.5f, 0.f, WA1, 640, 256);
    combine_w_kernel<<<dim3(8, 32), cw_blk>>>(aa_Wupd1, 512, 256, aa_Wsrc1, 256, 0.5f, 0.f, WA1, 640, 384);
    combine_b_kernel<<<1, 256>>>(ba_Wupd1, 512, ba_bsrc1, ba_bdst1, ba_bupd1, 0.5f, 0.f, bA1);
    combine_b_kernel<<<1, 256>>>(aa_Wupd1, 512, aa_bsrc1, aa_bdst1, aa_bupd1, 0.5f, 1.f, bA1);
    // Layer-1 B side: [x_B(128) | aggr_ab(256)], Ktot=384
    combine_w_kernel<<<dim3(4, 32), cw_blk>>>(ab_Wupd1, 512, 0,   ab_Wdst1, 128, 1.f, 0.f, WB1, 384, 0);
    combine_w_kernel<<<dim3(8, 32), cw_blk>>>(ab_Wupd1, 512, 256, ab_Wsrc1, 256, 1.f, 0.f, WB1, 384, 128);
    combine_b_kernel<<<1, 256>>>(ab_Wupd1, 512, ab_bsrc1, ab_bdst1, ab_bupd1, 1.f, 0.f, bB1);
    // Layer-2 A side: [hA(256) | aggr2_ba(256) | aggr2_aa(256)], Ktot=768 (convs 1=ba, 2=aa)
    combine_w_kernel<<<dim3(8, 32), cw_blk>>>(Wupd2 + 1 * 131072, 512, 0,   Wdst2 + 1 * 65536, 256, 0.5f, 0.f, WA2, 768, 0);
    combine_w_kernel<<<dim3(8, 32), cw_blk>>>(Wupd2 + 2 * 131072, 512, 0,   Wdst2 + 2 * 65536, 256, 0.5f, 1.f, WA2, 768, 0);
    combine_w_kernel<<<dim3(8, 32), cw_blk>>>(Wupd2 + 1 * 131072, 512, 256, Wsrc2 + 1 * 65536, 256, 0.5f, 0.f, WA2, 768, 256);
    combine_w_kernel<<<dim3(8, 32), cw_blk>>>(Wupd2 + 2 * 131072, 512, 256, Wsrc2 + 2 * 65536, 256, 0.5f, 0.f, WA2, 768, 512);
    combine_b_kernel<<<1, 256>>>(Wupd2 + 1 * 131072, 512, bsrc2 + 256, bdst2 + 256, bupd2 + 256, 0.5f, 0.f, bA2);
    combine_b_kernel<<<1, 256>>>(Wupd2 + 2 * 131072, 512, bsrc2 + 512, bdst2 + 512, bupd2 + 512, 0.5f, 1.f, bA2);
    // Layer-2 B side: [hB(256) | aggr2_ab(256)], Ktot=512 (conv 0=ab)
    combine_w_kernel<<<dim3(8, 32), cw_blk>>>(Wupd2, 512, 0,   Wdst2, 256, 1.f, 0.f, WB2, 512, 0);
    combine_w_kernel<<<dim3(8, 32), cw_blk>>>(Wupd2, 512, 256, Wsrc2, 256, 1.f, 0.f, WB2, 512, 256);
    combine_b_kernel<<<1, 256>>>(Wupd2, 512, bsrc2, bdst2, bupd2, 1.f, 0.f, bB2);

    // ---- layer 1: scatter-mean of raw features ----
    zero_kernel<<<ZB, 256>>>(aggr0, AGGR4);
    zero_kernel<<<ZB, 256>>>(aggr1, AGGR4);
    zero_kernel<<<ZB, 256>>>(aggr2, AGGR4);
    scatter256_kernel<<<(NE + 3) / 4, 256>>>(x_A, e_ab, e_ab + NE, aggr0, NE);
    scatter128_kernel<<<(NE + 7) / 8, 256>>>(x_B, e_ba, e_ba + NE, aggr1, NE);
    scatter256_kernel<<<(NE + 3) / 4, 256>>>(x_A, e_aa, e_aa + NE, aggr2, NE);
    normalize_kernel<<<(NN * 64 + 255) / 256, 256>>>(aggr0, cnt_ab, 64);
    normalize_kernel<<<(NN * 32 + 255) / 256, 256>>>(aggr1, cnt_ba, 32);
    normalize_kernel<<<(NN * 64 + 255) / 256, 256>>>(aggr2, cnt_aa, 64);

    // ---- layer 1 GEMMs ----
    dim3 ggrid(2, (NN + 127) / 128);
    gemm_kernel<<<ggrid, 256>>>(x_A, 256, aggr1, 128, aggr2, 256, WA1, bA1, preA, NN);
    gemm_kernel<<<ggrid, 256>>>(x_B, 128, aggr0, 256, nullptr, 0, WB1, bB1, preB, NN);

    // ---- layer 1 BN + LeakyReLU ----
    zero_kernel<<<1, 256>>>(stat, 128);
    stats_kernel<<<250, 256>>>(preA, NN, stat, stat + 256);
    bn_finalize_kernel<<<1, 256>>>(stat, stat + 256, bn_g + 0, bn_b + 0, NN, sc, sh);
    bn_apply_kernel<<<(NN * 64 + 255) / 256, 256>>>(preA, sc, sh, hA, NN);
    zero_kernel<<<1, 256>>>(stat, 128);
    stats_kernel<<<250, 256>>>(preB, NN, stat, stat + 256);
    bn_finalize_kernel<<<1, 256>>>(stat, stat + 256, bn_g + 256, bn_b + 256, NN, sc, sh);
    bn_apply_kernel<<<(NN * 64 + 255) / 256, 256>>>(preB, sc, sh, hB, NN);

    // ---- layer 2: scatter-mean of hidden features ----
    zero_kernel<<<ZB, 256>>>(aggr0, AGGR4);
    zero_kernel<<<ZB, 256>>>(aggr1, AGGR4);
    zero_kernel<<<ZB, 256>>>(aggr2, AGGR4);
    scatter256_kernel<<<(NE + 3) / 4, 256>>>(hA, e_ab, e_ab + NE, aggr0, NE);
    scatter256_kernel<<<(NE + 3) / 4, 256>>>(hB, e_ba, e_ba + NE, aggr1, NE);
    scatter256_kernel<<<(NE + 3) / 4, 256>>>(hA, e_aa, e_aa + NE, aggr2, NE);
    normalize_kernel<<<(NN * 64 + 255) / 256, 256>>>(aggr0, cnt_ab, 64);
    normalize_kernel<<<(NN * 64 + 255) / 256, 256>>>(aggr1, cnt_ba, 64);
    normalize_kernel<<<(NN * 64 + 255) / 256, 256>>>(aggr2, cnt_aa, 64);

    // ---- layer 2 GEMMs ----
    gemm_kernel<<<ggrid, 256>>>(hA, 256, aggr1, 256, aggr2, 256, WA2, bA2, preA, NN);
    gemm_kernel<<<ggrid, 256>>>(hB, 256, aggr0, 256, nullptr, 0, WB2, bB2, preB, NN);

    // ---- layer 2 BN + LeakyReLU -> d_out (outA then outB) ----
    zero_kernel<<<1, 256>>>(stat, 128);
    stats_kernel<<<250, 256>>>(preA, NN, stat, stat + 256);
    bn_finalize_kernel<<<1, 256>>>(stat, stat + 256, bn_g + 512, bn_b + 512, NN, sc, sh);
    bn_apply_kernel<<<(NN * 64 + 255) / 256, 256>>>(preA, sc, sh, out, NN);
    zero_kernel<<<1, 256>>>(stat, 128);
    stats_kernel<<<250, 256>>>(preB, NN, stat, stat + 256);
    bn_finalize_kernel<<<1, 256>>>(stat, stat + 256, bn_g + 768, bn_b + 768, NN, sc, sh);
    bn_apply_kernel<<<(NN * 64 + 255) / 256, 256>>>(preB, sc, sh, out + (size_t)NN * HD, NN);
}

// round 4
// speedup vs baseline: 2.0182x; 2.0182x over previous
#include <cuda_runtime.h>
#include <math.h>
#include <stdint.h>

#define NN 50000
#define NE 800000
#define HD  256
#define EPS_BN 1e-5f
#define SLOPE_LR 0.01f

// ---------------- scratch (__device__ globals; no allocation allowed) ----------------
__device__ float g_aggr0[(size_t)NN * HD];   // aggr for edge_ab (dst = B space)
__device__ float g_aggr1[(size_t)NN * HD];   // aggr for edge_ba (dst = A space)
__device__ float g_aggr2[(size_t)NN * HD];   // aggr for edge_aa (dst = A space)
__device__ float g_hA[(size_t)NN * HD];
__device__ float g_hB[(size_t)NN * HD];
__device__ float g_preA[(size_t)NN * HD];
__device__ float g_preB[(size_t)NN * HD];
__device__ float g_cnt[3 * NN];              // ab, ba, aa in-degree counts
__device__ float g_WA1[HD * 640];
__device__ float g_WB1[HD * 384];
__device__ float g_WA2[HD * 768];
__device__ float g_WB2[HD * 512];
__device__ float g_bA1[HD], g_bB1[HD], g_bA2[HD], g_bB2[HD];
__device__ float g_stat[2 * HD];             // col sums, col sumsq
__device__ float g_sc[HD], g_sh[HD];         // BN scale/shift

// ---------------- utility ----------------
__device__ __forceinline__ void red4(float* p, float4 v) {
    asm volatile("red.global.add.v4.f32 [%0], {%1,%2,%3,%4};"
                 :: "l"(p), "f"(v.x), "f"(v.y), "f"(v.z), "f"(v.w) : "memory");
}

__device__ __forceinline__ float to_tf32(float x) {
    uint32_t u;
    asm("cvt.rna.tf32.f32 %0, %1;" : "=r"(u) : "f"(x));
    return __uint_as_float(u);
}

__global__ void zero_kernel(float* __restrict__ p, int n4) {
    int i = blockIdx.x * blockDim.x + threadIdx.x;
    if (i < n4) reinterpret_cast<float4*>(p)[i] = make_float4(0.f, 0.f, 0.f, 0.f);
}

__global__ void count_kernel(const int* __restrict__ dst, float* __restrict__ cnt, int E) {
    int e = blockIdx.x * blockDim.x + threadIdx.x;
    if (e < E) atomicAdd(cnt + dst[e], 1.0f);
}

// D = 256 scatter-add: 4 edges per 256-thread block, 64 float4 chunks each
__global__ void scatter256_kernel(const float* __restrict__ feat,
                                  const int* __restrict__ src,
                                  const int* __restrict__ dst,
                                  float* __restrict__ out, int E) {
    int lane = threadIdx.x & 63;
    int slot = threadIdx.x >> 6;
    int e = blockIdx.x * 4 + slot;
    if (e >= E) return;
    int s = src[e];
    int d = dst[e];
    float4 v = reinterpret_cast<const float4*>(feat + (size_t)s * 256)[lane];
    red4(out + (size_t)d * 256 + lane * 4, v);
}

// D = 128 scatter-add: 8 edges per 256-thread block, 32 float4 chunks each
__global__ void scatter128_kernel(const float* __restrict__ feat,
                                  const int* __restrict__ src,
                                  const int* __restrict__ dst,
                                  float* __restrict__ out, int E) {
    int lane = threadIdx.x & 31;
    int slot = threadIdx.x >> 5;
    int e = blockIdx.x * 8 + slot;
    if (e >= E) return;
    int s = src[e];
    int d = dst[e];
    float4 v = reinterpret_cast<const float4*>(feat + (size_t)s * 128)[lane];
    red4(out + (size_t)d * 128 + lane * 4, v);
}

// out[o][ocoff+j] = beta*out[...] + scale * sum_i Wupd[o][coff+i] * Ws[i][j]
__global__ void combine_w_kernel(const float* __restrict__ Wupd, int wstride, int coff,
                                 const float* __restrict__ Ws, int d,
                                 float scale, float beta,
                                 float* __restrict__ out, int ostride, int ocoff) {
    int j = blockIdx.x * 32 + (threadIdx.x & 31);
    int o = blockIdx.y * 8 + (threadIdx.x >> 5);
    if (j >= d) return;
    float acc = 0.f;
    const float* wrow = Wupd + (size_t)o * wstride + coff;
#pragma unroll 4
    for (int i = 0; i < HD; i++)
        acc = fmaf(wrow[i], Ws[(size_t)i * d + j], acc);
    float* op = out + (size_t)o * ostride + ocoff + j;
    *op = beta * (*op) + scale * acc;
}

__global__ void combine_b_kernel(const float* __restrict__ Wupd, int wstride,
                                 const float* __restrict__ bsrc,
                                 const float* __restrict__ bdst,
                                 const float* __restrict__ bupd,
                                 float scale, float beta, float* __restrict__ out) {
    int o = threadIdx.x;
    float acc = bupd[o];
    const float* wrow = Wupd + (size_t)o * wstride;
#pragma unroll 4
    for (int i = 0; i < HD; i++)
        acc += wrow[i] * bdst[i] + wrow[HD + i] * bsrc[i];
    out[o] = beta * out[o] + scale * acc;
}

// ---------------- TF32 tensor-core GEMM ----------------
// C[M,256] = [A0|A1|A2] @ W^T + bias ; W is [256][Ktot] row-major; segmented K.
// Optional per-row scale (1/max(cnt,1)) per segment folds scatter-mean normalize in.
// Tile: 128x128x32, 256 threads (8 warps of 32x64), mma.m16n8k8 tf32.
__global__ __launch_bounds__(256) void gemm_tf32_kernel(
    const float* __restrict__ A0, int K0, const float* __restrict__ s0,
    const float* __restrict__ A1, int K1, const float* __restrict__ s1,
    const float* __restrict__ A2, int K2, const float* __restrict__ s2,
    const float* __restrict__ W, const float* __restrict__ bias,
    float* __restrict__ C, int M) {
    const int Ktot = K0 + K1 + K2;
    __shared__ float As[128][36];
    __shared__ float Bs[128][36];
    int tid = threadIdx.x;
    int m0 = blockIdx.y * 128;
    int n0 = blockIdx.x * 128;
    int warp = tid >> 5, lane = tid & 31;
    int wm = (warp & 3) * 32;      // warp m-offset in tile
    int wn = (warp >> 2) * 64;     // warp n-offset in tile
    int lr = lane >> 2;            // 0..7
    int lc = lane & 3;             // 0..3

    float acc[2][8][4];
#pragma unroll
    for (int mt = 0; mt < 2; mt++)
#pragma unroll
        for (int nt = 0; nt < 8; nt++)
#pragma unroll
            for (int q = 0; q < 4; q++) acc[mt][nt][q] = 0.f;

    for (int kb = 0; kb < Ktot; kb += 32) {
        // segment select (segment boundaries are multiples of 128; slab stays inside one)
        const float* Ap; const float* sp; int sw, kl;
        if (kb < K0)           { Ap = A0; sp = s0; sw = K0; kl = kb; }
        else if (kb < K0 + K1) { Ap = A1; sp = s1; sw = K1; kl = kb - K0; }
        else                   { Ap = A2; sp = s2; sw = K2; kl = kb - K0 - K1; }

        // load A tile: 128 rows x 32 k = 1024 float4 slots, 4 per thread
#pragma unroll
        for (int q = 0; q < 4; q++) {
            int s = tid + q * 256;
            int m = s >> 3;
            int kq = s & 7;
            int gm = m0 + m;
            float4 v = make_float4(0.f, 0.f, 0.f, 0.f);
            if (gm < M) {
                v = *reinterpret_cast<const float4*>(Ap + (size_t)gm * sw + kl + kq * 4);
                if (sp) {
                    float r = 1.0f / fmaxf(sp[gm], 1.0f);
                    v.x *= r; v.y *= r; v.z *= r; v.w *= r;
                }
            }
            As[m][kq * 4 + 0] = to_tf32(v.x);
            As[m][kq * 4 + 1] = to_tf32(v.y);
            As[m][kq * 4 + 2] = to_tf32(v.z);
            As[m][kq * 4 + 3] = to_tf32(v.w);
        }
        // load B tile (W rows n0..n0+127, k slab)
#pragma unroll
        for (int q = 0; q < 4; q++) {
            int s = tid + q * 256;
            int n = s >> 3;
            int kq = s & 7;
            int gn = n0 + n;
            float4 v = *reinterpret_cast<const float4*>(W + (size_t)gn * Ktot + kb + kq * 4);
            Bs[n][kq * 4 + 0] = to_tf32(v.x);
            Bs[n][kq * 4 + 1] = to_tf32(v.y);
            Bs[n][kq * 4 + 2] = to_tf32(v.z);
            Bs[n][kq * 4 + 3] = to_tf32(v.w);
        }
        __syncthreads();

#pragma unroll
        for (int ks = 0; ks < 4; ks++) {
            int k0 = ks * 8;
            uint32_t af[2][4];
#pragma unroll
            for (int mt = 0; mt < 2; mt++) {
                int row = wm + mt * 16 + lr;
                af[mt][0] = __float_as_uint(As[row][k0 + lc]);
                af[mt][1] = __float_as_uint(As[row + 8][k0 + lc]);
                af[mt][2] = __float_as_uint(As[row][k0 + 4 + lc]);
                af[mt][3] = __float_as_uint(As[row + 8][k0 + 4 + lc]);
            }
#pragma unroll
            for (int nt = 0; nt < 8; nt++) {
                int col = wn + nt * 8 + lr;
                uint32_t b0 = __float_as_uint(Bs[col][k0 + lc]);
                uint32_t b1 = __float_as_uint(Bs[col][k0 + 4 + lc]);
#pragma unroll
                for (int mt = 0; mt < 2; mt++) {
                    asm volatile(
                        "mma.sync.aligned.m16n8k8.row.col.f32.tf32.tf32.f32 "
                        "{%0,%1,%2,%3}, {%4,%5,%6,%7}, {%8,%9}, {%0,%1,%2,%3};"
                        : "+f"(acc[mt][nt][0]), "+f"(acc[mt][nt][1]),
                          "+f"(acc[mt][nt][2]), "+f"(acc[mt][nt][3])
                        : "r"(af[mt][0]), "r"(af[mt][1]), "r"(af[mt][2]), "r"(af[mt][3]),
                          "r"(b0), "r"(b1));
                }
            }
        }
        __syncthreads();
    }

    // epilogue: d layout c0,c1 at (row=lr, col=lc*2,+1); c2,c3 at row+8
#pragma unroll
    for (int mt = 0; mt < 2; mt++) {
#pragma unroll
        for (int nt = 0; nt < 8; nt++) {
            int gn = n0 + wn + nt * 8 + lc * 2;
            int gm = m0 + wm + mt * 16 + lr;
            float b0 = bias[gn], b1 = bias[gn + 1];
            if (gm < M) {
                float2 o = make_float2(acc[mt][nt][0] + b0, acc[mt][nt][1] + b1);
                *reinterpret_cast<float2*>(C + (size_t)gm * 256 + gn) = o;
            }
            if (gm + 8 < M) {
                float2 o = make_float2(acc[mt][nt][2] + b0, acc[mt][nt][3] + b1);
                *reinterpret_cast<float2*>(C + (size_t)(gm + 8) * 256 + gn) = o;
            }
        }
    }
}

// column-wise sum / sumsq partials (coalesced: thread t handles column t)
__global__ void stats_kernel(const float* __restrict__ X, int M,
                             float* __restrict__ s, float* __restrict__ s2) {
    int t = threadIdx.x;
    int rows_per = (M + gridDim.x - 1) / gridDim.x;
    int r0 = blockIdx.x * rows_per;
    int r1 = min(r0 + rows_per, M);
    float a = 0.f, b = 0.f;
    for (int r = r0; r < r1; r++) {
        float v = X[(size_t)r * 256 + t];
        a += v;
        b += v * v;
    }
    atomicAdd(s + t, a);
    atomicAdd(s2 + t, b);
}

__global__ void bn_finalize_kernel(const float* __restrict__ s, const float* __restrict__ s2,
                                   const float* __restrict__ g, const float* __restrict__ bb,
                                   int M, float* __restrict__ sc, float* __restrict__ sh) {
    int t = threadIdx.x;
    float mean = s[t] / (float)M;
    float var = s2[t] / (float)M - mean * mean;
    float a = g[t] * rsqrtf(var + EPS_BN);
    sc[t] = a;
    sh[t] = bb[t] - mean * a;
}

__global__ void bn_apply_kernel(const float* __restrict__ X,
                                const float* __restrict__ sc, const float* __restrict__ sh,
                                float* __restrict__ Y, int M) {
    int i = blockIdx.x * blockDim.x + threadIdx.x;
    if (i >= M * 64) return;
    int c4 = i & 63;
    float4 a = reinterpret_cast<const float4*>(sc)[c4];
    float4 c = reinterpret_cast<const float4*>(sh)[c4];
    float4 x = reinterpret_cast<const float4*>(X)[i];
    float4 y;
    y.x = a.x * x.x + c.x; y.x = y.x > 0.f ? y.x : SLOPE_LR * y.x;
    y.y = a.y * x.y + c.y; y.y = y.y > 0.f ? y.y : SLOPE_LR * y.y;
    y.z = a.z * x.z + c.z; y.z = y.z > 0.f ? y.z : SLOPE_LR * y.z;
    y.w = a.w * x.w + c.w; y.w = y.w > 0.f ? y.w : SLOPE_LR * y.w;
    reinterpret_cast<float4*>(Y)[i] = y;
}

// ---------------- host orchestration ----------------
static inline float* sym(const void* s) {
    void* p = nullptr;
    cudaGetSymbolAddress(&p, s);
    return (float*)p;
}

extern "C" void kernel_launch(void* const* d_in, const int* in_sizes, int n_in,
                              void* d_out, int out_size) {
    (void)in_sizes; (void)n_in; (void)out_size;
    const float* x_A = (const float*)d_in[0];
    const float* x_B = (const float*)d_in[1];
    const int* e_ab = (const int*)d_in[2];
    const int* e_ba = (const int*)d_in[3];
    const int* e_aa = (const int*)d_in[4];
    const float* ab_Wsrc1 = (const float*)d_in[5];
    const float* ab_bsrc1 = (const float*)d_in[6];
    const float* ab_Wdst1 = (const float*)d_in[7];
    const float* ab_bdst1 = (const float*)d_in[8];
    const float* ab_Wupd1 = (const float*)d_in[9];
    const float* ab_bupd1 = (const float*)d_in[10];
    const float* ba_Wsrc1 = (const float*)d_in[11];
    const float* ba_bsrc1 = (const float*)d_in[12];
    const float* ba_Wdst1 = (const float*)d_in[13];
    const float* ba_bdst1 = (const float*)d_in[14];
    const float* ba_Wupd1 = (const float*)d_in[15];
    const float* ba_bupd1 = (const float*)d_in[16];
    const float* aa_Wsrc1 = (const float*)d_in[17];
    const float* aa_bsrc1 = (const float*)d_in[18];
    const float* aa_Wdst1 = (const float*)d_in[19];
    const float* aa_bdst1 = (const float*)d_in[20];
    const float* aa_Wupd1 = (const float*)d_in[21];
    const float* aa_bupd1 = (const float*)d_in[22];
    const float* Wsrc2 = (const float*)d_in[23];
    const float* bsrc2 = (const float*)d_in[24];
    const float* Wdst2 = (const float*)d_in[25];
    const float* bdst2 = (const float*)d_in[26];
    const float* Wupd2 = (const float*)d_in[27];
    const float* bupd2 = (const float*)d_in[28];
    const float* bn_g = (const float*)d_in[29];
    const float* bn_b = (const float*)d_in[30];
    float* out = (float*)d_out;

    float* aggr0 = sym(g_aggr0);
    float* aggr1 = sym(g_aggr1);
    float* aggr2 = sym(g_aggr2);
    float* hA = sym(g_hA);
    float* hB = sym(g_hB);
    float* preA = sym(g_preA);
    float* preB = sym(g_preB);
    float* cnt = sym(g_cnt);
    float* WA1 = sym(g_WA1);
    float* WB1 = sym(g_WB1);
    float* WA2 = sym(g_WA2);
    float* WB2 = sym(g_WB2);
    float* bA1 = sym(g_bA1);
    float* bB1 = sym(g_bB1);
    float* bA2 = sym(g_bA2);
    float* bB2 = sym(g_bB2);
    float* stat = sym(g_stat);
    float* sc = sym(g_sc);
    float* sh = sym(g_sh);

    float* cnt_ab = cnt;
    float* cnt_ba = cnt + NN;
    float* cnt_aa = cnt + 2 * NN;

    const int AGGR4 = NN * HD / 4;
    const int ZB = (AGGR4 + 255) / 256;
    dim3 cw_blk(256);

    // ---- degree counts (shared by both layers) ----
    zero_kernel<<<((3 * NN / 4) + 255) / 256, 256>>>(cnt, 3 * NN / 4);
    count_kernel<<<(NE + 255) / 256, 256>>>(e_ab + NE, cnt_ab, NE);
    count_kernel<<<(NE + 255) / 256, 256>>>(e_ba + NE, cnt_ba, NE);
    count_kernel<<<(NE + 255) / 256, 256>>>(e_aa + NE, cnt_aa, NE);

    // ---- combined weights ----
    combine_w_kernel<<<dim3(8, 32), cw_blk>>>(ba_Wupd1, 512, 0,   ba_Wdst1, 256, 0.5f, 0.f, WA1, 640, 0);
    combine_w_kernel<<<dim3(8, 32), cw_blk>>>(aa_Wupd1, 512, 0,   aa_Wdst1, 256, 0.5f, 1.f, WA1, 640, 0);
    combine_w_kernel<<<dim3(4, 32), cw_blk>>>(ba_Wupd1, 512, 256, ba_Wsrc1, 128, 0.5f, 0.f, WA1, 640, 256);
    combine_w_kernel<<<dim3(8, 32), cw_blk>>>(aa_Wupd1, 512, 256, aa_Wsrc1, 256, 0.5f, 0.f, WA1, 640, 384);
    combine_b_kernel<<<1, 256>>>(ba_Wupd1, 512, ba_bsrc1, ba_bdst1, ba_bupd1, 0.5f, 0.f, bA1);
    combine_b_kernel<<<1, 256>>>(aa_Wupd1, 512, aa_bsrc1, aa_bdst1, aa_bupd1, 0.5f, 1.f, bA1);
    combine_w_kernel<<<dim3(4, 32), cw_blk>>>(ab_Wupd1, 512, 0,   ab_Wdst1, 128, 1.f, 0.f, WB1, 384, 0);
    combine_w_kernel<<<dim3(8, 32), cw_blk>>>(ab_Wupd1, 512, 256, ab_Wsrc1, 256, 1.f, 0.f, WB1, 384, 128);
    combine_b_kernel<<<1, 256>>>(ab_Wupd1, 512, ab_bsrc1, ab_bdst1, ab_bupd1, 1.f, 0.f, bB1);
    combine_w_kernel<<<dim3(8, 32), cw_blk>>>(Wupd2 + 1 * 131072, 512, 0,   Wdst2 + 1 * 65536, 256, 0.5f, 0.f, WA2, 768, 0);
    combine_w_kernel<<<dim3(8, 32), cw_blk>>>(Wupd2 + 2 * 131072, 512, 0,   Wdst2 + 2 * 65536, 256, 0.5f, 1.f, WA2, 768, 0);
    combine_w_kernel<<<dim3(8, 32), cw_blk>>>(Wupd2 + 1 * 131072, 512, 256, Wsrc2 + 1 * 65536, 256, 0.5f, 0.f, WA2, 768, 256);
    combine_w_kernel<<<dim3(8, 32), cw_blk>>>(Wupd2 + 2 * 131072, 512, 256, Wsrc2 + 2 * 65536, 256, 0.5f, 0.f, WA2, 768, 512);
    combine_b_kernel<<<1, 256>>>(Wupd2 + 1 * 131072, 512, bsrc2 + 256, bdst2 + 256, bupd2 + 256, 0.5f, 0.f, bA2);
    combine_b_kernel<<<1, 256>>>(Wupd2 + 2 * 131072, 512, bsrc2 + 512, bdst2 + 512, bupd2 + 512, 0.5f, 1.f, bA2);
    combine_w_kernel<<<dim3(8, 32), cw_blk>>>(Wupd2, 512, 0,   Wdst2, 256, 1.f, 0.f, WB2, 512, 0);
    combine_w_kernel<<<dim3(8, 32), cw_blk>>>(Wupd2, 512, 256, Wsrc2, 256, 1.f, 0.f, WB2, 512, 256);
    combine_b_kernel<<<1, 256>>>(Wupd2, 512, bsrc2, bdst2, bupd2, 1.f, 0.f, bB2);

    // ---- layer 1: scatter-sum of raw features (mean folded into GEMM) ----
    zero_kernel<<<ZB, 256>>>(aggr0, AGGR4);
    zero_kernel<<<ZB, 256>>>(aggr1, AGGR4);
    zero_kernel<<<ZB, 256>>>(aggr2, AGGR4);
    scatter256_kernel<<<(NE + 3) / 4, 256>>>(x_A, e_ab, e_ab + NE, aggr0, NE);
    scatter128_kernel<<<(NE + 7) / 8, 256>>>(x_B, e_ba, e_ba + NE, aggr1, NE);
    scatter256_kernel<<<(NE + 3) / 4, 256>>>(x_A, e_aa, e_aa + NE, aggr2, NE);

    // ---- layer 1 GEMMs (tf32 tensor cores) ----
    dim3 ggrid(2, (NN + 127) / 128);
    gemm_tf32_kernel<<<ggrid, 256>>>(x_A, 256, nullptr, aggr1, 128, cnt_ba,
                                     aggr2, 256, cnt_aa, WA1, bA1, preA, NN);
    gemm_tf32_kernel<<<ggrid, 256>>>(x_B, 128, nullptr, aggr0, 256, cnt_ab,
                                     nullptr, 0, nullptr, WB1, bB1, preB, NN);

    // ---- layer 1 BN + LeakyReLU ----
    zero_kernel<<<1, 256>>>(stat, 128);
    stats_kernel<<<250, 256>>>(preA, NN, stat, stat + 256);
    bn_finalize_kernel<<<1, 256>>>(stat, stat + 256, bn_g + 0, bn_b + 0, NN, sc, sh);
    bn_apply_kernel<<<(NN * 64 + 255) / 256, 256>>>(preA, sc, sh, hA, NN);
    zero_kernel<<<1, 256>>>(stat, 128);
    stats_kernel<<<250, 256>>>(preB, NN, stat, stat + 256);
    bn_finalize_kernel<<<1, 256>>>(stat, stat + 256, bn_g + 256, bn_b + 256, NN, sc, sh);
    bn_apply_kernel<<<(NN * 64 + 255) / 256, 256>>>(preB, sc, sh, hB, NN);

    // ---- layer 2: scatter-sum of hidden features ----
    zero_kernel<<<ZB, 256>>>(aggr0, AGGR4);
    zero_kernel<<<ZB, 256>>>(aggr1, AGGR4);
    zero_kernel<<<ZB, 256>>>(aggr2, AGGR4);
    scatter256_kernel<<<(NE + 3) / 4, 256>>>(hA, e_ab, e_ab + NE, aggr0, NE);
    scatter256_kernel<<<(NE + 3) / 4, 256>>>(hB, e_ba, e_ba + NE, aggr1, NE);
    scatter256_kernel<<<(NE + 3) / 4, 256>>>(hA, e_aa, e_aa + NE, aggr2, NE);

    // ---- layer 2 GEMMs ----
    gemm_tf32_kernel<<<ggrid, 256>>>(hA, 256, nullptr, aggr1, 256, cnt_ba,
                                     aggr2, 256, cnt_aa, WA2, bA2, preA, NN);
    gemm_tf32_kernel<<<ggrid, 256>>>(hB, 256, nullptr, aggr0, 256, cnt_ab,
                                     nullptr, 0, nullptr, WB2, bB2, preB, NN);

    // ---- layer 2 BN + LeakyReLU -> d_out (outA then outB) ----
    zero_kernel<<<1, 256>>>(stat, 128);
    stats_kernel<<<250, 256>>>(preA, NN, stat, stat + 256);
    bn_finalize_kernel<<<1, 256>>>(stat, stat + 256, bn_g + 512, bn_b + 512, NN, sc, sh);
    bn_apply_kernel<<<(NN * 64 + 255) / 256, 256>>>(preA, sc, sh, out, NN);
    zero_kernel<<<1, 256>>>(stat, 128);
    stats_kernel<<<250, 256>>>(preB, NN, stat, stat + 256);
    bn_finalize_kernel<<<1, 256>>>(stat, stat + 256, bn_g + 768, bn_b + 768, NN, sc, sh);
    bn_apply_kernel<<<(NN * 64 + 255) / 256, 256>>>(preB, sc, sh, out + (size_t)NN * HD, NN);
}

// round 6
// speedup vs baseline: 2.6331x; 1.3047x over previous
#include <cuda_runtime.h>
#include <math.h>
#include <stdint.h>

#define NN 50000
#define NE 800000
#define HD  256
#define EPS_BN 1e-5f
#define SLOPE_LR 0.01f
#define STATS_BLKS 250

// ---------------- scratch (__device__ globals; no allocation allowed) ----------------
__device__ float g_aggr0[(size_t)NN * HD];   // ab aggregation (dst = B space)
__device__ float g_aggr1[(size_t)NN * HD];   // ba aggregation (dst = A space)
__device__ float g_aggr2[(size_t)NN * HD];   // aa aggregation (dst = A space)
__device__ float g_hA[(size_t)NN * HD];
__device__ float g_hB[(size_t)NN * HD];
__device__ float g_preA[(size_t)NN * HD];
__device__ float g_preB[(size_t)NN * HD];
__device__ float g_xAt[(size_t)NN * 256];    // tf32-rounded x_A
__device__ float g_xBt[(size_t)NN * 128];    // tf32-rounded x_B
__device__ int   g_icnt[3 * NN];             // degree counts, then reused as fill cursors
__device__ int   g_roff[3 * (NN + 1)];
__device__ int   g_csr[3 * NE];
__device__ float g_WA1[HD * 640];
__device__ float g_WB1[HD * 384];
__device__ float g_WA2[HD * 768];
__device__ float g_WB2[HD * 512];
__device__ float g_bA1[HD], g_bB1[HD], g_bA2[HD], g_bB2[HD];
__device__ float g_part[STATS_BLKS * 512];   // per-block col sum/sumsq partials
__device__ float g_sc[HD], g_sh[HD];         // BN scale/shift

// ---------------- utility ----------------
__device__ __forceinline__ float to_tf32(float x) {
    uint32_t u;
    asm("cvt.rna.tf32.f32 %0, %1;" : "=r"(u) : "f"(x));
    return __uint_as_float(u);
}

__global__ void zero_int_kernel(int* __restrict__ p, int n) {
    int i = blockIdx.x * blockDim.x + threadIdx.x;
    if (i < n) p[i] = 0;
}

__global__ void count_int_kernel(const int* __restrict__ dst, int* __restrict__ cnt, int E) {
    int e = blockIdx.x * blockDim.x + threadIdx.x;
    if (e < E) atomicAdd(cnt + dst[e], 1);
}

// single-block exclusive scan of NN ints -> roff[NN+1]; then RESET cnt to 0 so the
// same array serves as the fill cursor (no cross-symbol layout assumptions).
__global__ void scan_kernel(int* __restrict__ cnt, int* __restrict__ roff) {
    __shared__ int sm[1024];
    __shared__ int carry_s;
    int tid = threadIdx.x;
    if (tid == 0) { carry_s = 0; roff[0] = 0; }
    __syncthreads();
    for (int base = 0; base < NN; base += 1024) {
        int i = base + tid;
        int v = (i < NN) ? cnt[i] : 0;
        sm[tid] = v;
        __syncthreads();
#pragma unroll
        for (int off = 1; off < 1024; off <<= 1) {
            int t = (tid >= off) ? sm[tid - off] : 0;
            __syncthreads();
            sm[tid] += t;
            __syncthreads();
        }
        if (i < NN) {
            roff[i + 1] = carry_s + sm[tid];
            cnt[i] = 0;                      // reset for reuse as fill cursor
        }
        __syncthreads();
        if (tid == 0) carry_s += sm[1023];
        __syncthreads();
    }
}

__global__ void fill_kernel(const int* __restrict__ src, const int* __restrict__ dst,
                            const int* __restrict__ roff, int* __restrict__ fill,
                            int* __restrict__ csr, int E) {
    int e = blockIdx.x * blockDim.x + threadIdx.x;
    if (e >= E) return;
    int d = dst[e];
    int pos = roff[d] + atomicAdd(fill + d, 1);
    csr[pos] = src[e];
}

// gather-mean over CSR, 256-dim rows: 4 nodes per 256-thread block, 64 lanes each.
// Output rounded to tf32 (feeds the GEMM directly).
__global__ void gather256_kernel(const float* __restrict__ feat,
                                 const int* __restrict__ roff,
                                 const int* __restrict__ csr,
                                 float* __restrict__ out) {
    int node = blockIdx.x * 4 + (threadIdx.x >> 6);
    int lane = threadIdx.x & 63;
    if (node >= NN) return;
    int j0 = roff[node], j1 = roff[node + 1];
    const float4* f = reinterpret_cast<const float4*>(feat);
    float4 acc = make_float4(0.f, 0.f, 0.f, 0.f);
    int j = j0;
    for (; j + 1 < j1; j += 2) {
        int s0 = csr[j], s1 = csr[j + 1];
        float4 a = f[(size_t)s0 * 64 + lane];
        float4 b = f[(size_t)s1 * 64 + lane];
        acc.x += a.x; acc.y += a.y; acc.z += a.z; acc.w += a.w;
        acc.x += b.x; acc.y += b.y; acc.z += b.z; acc.w += b.w;
    }
    if (j < j1) {
        int s = csr[j];
        float4 a = f[(size_t)s * 64 + lane];
        acc.x += a.x; acc.y += a.y; acc.z += a.z; acc.w += a.w;
    }
    float r = 1.0f / (float)max(j1 - j0, 1);
    float4 o;
    o.x = to_tf32(acc.x * r); o.y = to_tf32(acc.y * r);
    o.z = to_tf32(acc.z * r); o.w = to_tf32(acc.w * r);
    reinterpret_cast<float4*>(out)[(size_t)node * 64 + lane] = o;
}

// gather-mean, 128-dim rows: 8 nodes per 256-thread block, 32 lanes each.
__global__ void gather128_kernel(const float* __restrict__ feat,
                                 const int* __restrict__ roff,
                                 const int* __restrict__ csr,
                                 float* __restrict__ out) {
    int node = blockIdx.x * 8 + (threadIdx.x >> 5);
    int lane = threadIdx.x & 31;
    if (node >= NN) return;
    int j0 = roff[node], j1 = roff[node + 1];
    const float4* f = reinterpret_cast<const float4*>(feat);
    float4 acc = make_float4(0.f, 0.f, 0.f, 0.f);
    int j = j0;
    for (; j + 1 < j1; j += 2) {
        int s0 = csr[j], s1 = csr[j + 1];
        float4 a = f[(size_t)s0 * 32 + lane];
        float4 b = f[(size_t)s1 * 32 + lane];
        acc.x += a.x; acc.y += a.y; acc.z += a.z; acc.w += a.w;
        acc.x += b.x; acc.y += b.y; acc.z += b.z; acc.w += b.w;
    }
    if (j < j1) {
        int s = csr[j];
        float4 a = f[(size_t)s * 32 + lane];
        acc.x += a.x; acc.y += a.y; acc.z += a.z; acc.w += a.w;
    }
    float r = 1.0f / (float)max(j1 - j0, 1);
    float4 o;
    o.x = to_tf32(acc.x * r); o.y = to_tf32(acc.y * r);
    o.z = to_tf32(acc.z * r); o.w = to_tf32(acc.w * r);
    reinterpret_cast<float4*>(out)[(size_t)node * 32 + lane] = o;
}

// round fp32 buffer to tf32 (one-time copies of x_A / x_B)
__global__ void round_kernel(const float* __restrict__ in, float* __restrict__ out, int n4) {
    int i = blockIdx.x * blockDim.x + threadIdx.x;
    if (i >= n4) return;
    float4 v = reinterpret_cast<const float4*>(in)[i];
    float4 o;
    o.x = to_tf32(v.x); o.y = to_tf32(v.y); o.z = to_tf32(v.z); o.w = to_tf32(v.w);
    reinterpret_cast<float4*>(out)[i] = o;
}

// out[o][ocoff+j] = tf32( beta*out[...] + scale * sum_i Wupd[o][coff+i] * Ws[i][j] )
__global__ void combine_w_kernel(const float* __restrict__ Wupd, int wstride, int coff,
                                 const float* __restrict__ Ws, int d,
                                 float scale, float beta,
                                 float* __restrict__ out, int ostride, int ocoff) {
    int j = blockIdx.x * 32 + (threadIdx.x & 31);
    int o = blockIdx.y * 8 + (threadIdx.x >> 5);
    if (j >= d) return;
    float acc = 0.f;
    const float* wrow = Wupd + (size_t)o * wstride + coff;
#pragma unroll 4
    for (int i = 0; i < HD; i++)
        acc = fmaf(wrow[i], Ws[(size_t)i * d + j], acc);
    float* op = out + (size_t)o * ostride + ocoff + j;
    *op = to_tf32(beta * (*op) + scale * acc);
}

__global__ void combine_b_kernel(const float* __restrict__ Wupd, int wstride,
                                 const float* __restrict__ bsrc,
                                 const float* __restrict__ bdst,
                                 const float* __restrict__ bupd,
                                 float scale, float beta, float* __restrict__ out) {
    int o = threadIdx.x;
    float acc = bupd[o];
    const float* wrow = Wupd + (size_t)o * wstride;
#pragma unroll 4
    for (int i = 0; i < HD; i++)
        acc += wrow[i] * bdst[i] + wrow[HD + i] * bsrc[i];
    out[o] = beta * out[o] + scale * acc;
}

// ---------------- TF32 tensor-core GEMM ----------------
// C[M,256] = [A0|A1|A2] @ W^T + bias. All inputs already tf32-rounded.
// Tile 128x128x32, 256 threads, register-prefetch pipelined global loads.
__global__ __launch_bounds__(256) void gemm_tf32_kernel(
    const float* __restrict__ A0, int K0,
    const float* __restrict__ A1, int K1,
    const float* __restrict__ A2, int K2,
    const float* __restrict__ W, const float* __restrict__ bias,
    float* __restrict__ C, int M) {
    const int Ktot = K0 + K1 + K2;
    __shared__ float As[128][36];
    __shared__ float Bs[128][36];
    int tid = threadIdx.x;
    int m0 = blockIdx.y * 128;
    int n0 = blockIdx.x * 128;
    int warp = tid >> 5, lane = tid & 31;
    int wm = (warp & 3) * 32;
    int wn = (warp >> 2) * 64;
    int lr = lane >> 2;
    int lc = lane & 3;

    float acc[2][8][4];
#pragma unroll
    for (int mt = 0; mt < 2; mt++)
#pragma unroll
        for (int nt = 0; nt < 8; nt++)
#pragma unroll
            for (int q = 0; q < 4; q++) acc[mt][nt][q] = 0.f;

    float4 ra[4], rb[4];
    auto load_slab = [&](int kb) {
        const float* Ap; int sw, kl;
        if (kb < K0)           { Ap = A0; sw = K0; kl = kb; }
        else if (kb < K0 + K1) { Ap = A1; sw = K1; kl = kb - K0; }
        else                   { Ap = A2; sw = K2; kl = kb - K0 - K1; }
#pragma unroll
        for (int q = 0; q < 4; q++) {
            int s = tid + q * 256;
            int m = s >> 3;
            int kq = s & 7;
            int gm = m0 + m;
            ra[q] = (gm < M) ? *reinterpret_cast<const float4*>(Ap + (size_t)gm * sw + kl + kq * 4)
                             : make_float4(0.f, 0.f, 0.f, 0.f);
            int gn = n0 + m;
            rb[q] = *reinterpret_cast<const float4*>(W + (size_t)gn * Ktot + kb + kq * 4);
        }
    };

    load_slab(0);
    for (int kb = 0; kb < Ktot; kb += 32) {
#pragma unroll
        for (int q = 0; q < 4; q++) {
            int s = tid + q * 256;
            int m = s >> 3;
            int kq = s & 7;
            As[m][kq * 4 + 0] = ra[q].x; As[m][kq * 4 + 1] = ra[q].y;
            As[m][kq * 4 + 2] = ra[q].z; As[m][kq * 4 + 3] = ra[q].w;
            Bs[m][kq * 4 + 0] = rb[q].x; Bs[m][kq * 4 + 1] = rb[q].y;
            Bs[m][kq * 4 + 2] = rb[q].z; Bs[m][kq * 4 + 3] = rb[q].w;
        }
        __syncthreads();
        if (kb + 32 < Ktot) load_slab(kb + 32);   // overlap next loads with mma

#pragma unroll
        for (int ks = 0; ks < 4; ks++) {
            int k0 = ks * 8;
            uint32_t af[2][4];
#pragma unroll
            for (int mt = 0; mt < 2; mt++) {
                int row = wm + mt * 16 + lr;
                af[mt][0] = __float_as_uint(As[row][k0 + lc]);
                af[mt][1] = __float_as_uint(As[row + 8][k0 + lc]);
                af[mt][2] = __float_as_uint(As[row][k0 + 4 + lc]);
                af[mt][3] = __float_as_uint(As[row + 8][k0 + 4 + lc]);
            }
#pragma unroll
            for (int nt = 0; nt < 8; nt++) {
                int col = wn + nt * 8 + lr;
                uint32_t b0 = __float_as_uint(Bs[col][k0 + lc]);
                uint32_t b1 = __float_as_uint(Bs[col][k0 + 4 + lc]);
#pragma unroll
                for (int mt = 0; mt < 2; mt++) {
                    asm volatile(
                        "mma.sync.aligned.m16n8k8.row.col.f32.tf32.tf32.f32 "
                        "{%0,%1,%2,%3}, {%4,%5,%6,%7}, {%8,%9}, {%0,%1,%2,%3};"
                        : "+f"(acc[mt][nt][0]), "+f"(acc[mt][nt][1]),
                          "+f"(acc[mt][nt][2]), "+f"(acc[mt][nt][3])
                        : "r"(af[mt][0]), "r"(af[mt][1]), "r"(af[mt][2]), "r"(af[mt][3]),
                          "r"(b0), "r"(b1));
                }
            }
        }
        __syncthreads();
    }

#pragma unroll
    for (int mt = 0; mt < 2; mt++) {
#pragma unroll
        for (int nt = 0; nt < 8; nt++) {
            int gn = n0 + wn + nt * 8 + lc * 2;
            int gm = m0 + wm + mt * 16 + lr;
            float b0 = bias[gn], b1 = bias[gn + 1];
            if (gm < M) {
                float2 o = make_float2(acc[mt][nt][0] + b0, acc[mt][nt][1] + b1);
                *reinterpret_cast<float2*>(C + (size_t)gm * 256 + gn) = o;
            }
            if (gm + 8 < M) {
                float2 o = make_float2(acc[mt][nt][2] + b0, acc[mt][nt][3] + b1);
                *reinterpret_cast<float2*>(C + (size_t)(gm + 8) * 256 + gn) = o;
            }
        }
    }
}

// column-wise sum / sumsq partials into distinct slots (deterministic, no atomics)
__global__ void stats_kernel(const float* __restrict__ X, int M, float* __restrict__ part) {
    int t = threadIdx.x;
    int rows_per = (M + gridDim.x - 1) / gridDim.x;
    int r0 = blockIdx.x * rows_per;
    int r1 = min(r0 + rows_per, M);
    float a = 0.f, b = 0.f;
    for (int r = r0; r < r1; r++) {
        float v = X[(size_t)r * 256 + t];
        a += v;
        b += v * v;
    }
    part[blockIdx.x * 512 + t] = a;
    part[blockIdx.x * 512 + 256 + t] = b;
}

__global__ void bn_finalize_kernel(const float* __restrict__ part,
                                   const float* __restrict__ g, const float* __restrict__ bb,
                                   int M, float* __restrict__ sc, float* __restrict__ sh) {
    int t = threadIdx.x;
    float s = 0.f, s2 = 0.f;
    for (int blk = 0; blk < STATS_BLKS; blk++) {
        s += part[blk * 512 + t];
        s2 += part[blk * 512 + 256 + t];
    }
    float mean = s / (float)M;
    float var = s2 / (float)M - mean * mean;
    float a = g[t] * rsqrtf(var + EPS_BN);
    sc[t] = a;
    sh[t] = bb[t] - mean * a;
}

__global__ void bn_apply_kernel(const float* __restrict__ X,
                                const float* __restrict__ sc, const float* __restrict__ sh,
                                float* __restrict__ Y, int M, int do_round) {
    int i = blockIdx.x * blockDim.x + threadIdx.x;
    if (i >= M * 64) return;
    int c4 = i & 63;
    float4 a = reinterpret_cast<const float4*>(sc)[c4];
    float4 c = reinterpret_cast<const float4*>(sh)[c4];
    float4 x = reinterpret_cast<const float4*>(X)[i];
    float4 y;
    y.x = a.x * x.x + c.x; y.x = y.x > 0.f ? y.x : SLOPE_LR * y.x;
    y.y = a.y * x.y + c.y; y.y = y.y > 0.f ? y.y : SLOPE_LR * y.y;
    y.z = a.z * x.z + c.z; y.z = y.z > 0.f ? y.z : SLOPE_LR * y.z;
    y.w = a.w * x.w + c.w; y.w = y.w > 0.f ? y.w : SLOPE_LR * y.w;
    if (do_round) {
        y.x = to_tf32(y.x); y.y = to_tf32(y.y); y.z = to_tf32(y.z); y.w = to_tf32(y.w);
    }
    reinterpret_cast<float4*>(Y)[i] = y;
}

// ---------------- host orchestration ----------------
static inline float* symf(const void* s) {
    void* p = nullptr;
    cudaGetSymbolAddress(&p, s);
    return (float*)p;
}
static inline int* symi(const void* s) {
    void* p = nullptr;
    cudaGetSymbolAddress(&p, s);
    return (int*)p;
}

extern "C" void kernel_launch(void* const* d_in, const int* in_sizes, int n_in,
                              void* d_out, int out_size) {
    (void)in_sizes; (void)n_in; (void)out_size;
    const float* x_A = (const float*)d_in[0];
    const float* x_B = (const float*)d_in[1];
    const int* e_ab = (const int*)d_in[2];
    const int* e_ba = (const int*)d_in[3];
    const int* e_aa = (const int*)d_in[4];
    const float* ab_Wsrc1 = (const float*)d_in[5];
    const float* ab_bsrc1 = (const float*)d_in[6];
    const float* ab_Wdst1 = (const float*)d_in[7];
    const float* ab_bdst1 = (const float*)d_in[8];
    const float* ab_Wupd1 = (const float*)d_in[9];
    const float* ab_bupd1 = (const float*)d_in[10];
    const float* ba_Wsrc1 = (const float*)d_in[11];
    const float* ba_bsrc1 = (const float*)d_in[12];
    const float* ba_Wdst1 = (const float*)d_in[13];
    const float* ba_bdst1 = (const float*)d_in[14];
    const float* ba_Wupd1 = (const float*)d_in[15];
    const float* ba_bupd1 = (const float*)d_in[16];
    const float* aa_Wsrc1 = (const float*)d_in[17];
    const float* aa_bsrc1 = (const float*)d_in[18];
    const float* aa_Wdst1 = (const float*)d_in[19];
    const float* aa_bdst1 = (const float*)d_in[20];
    const float* aa_Wupd1 = (const float*)d_in[21];
    const float* aa_bupd1 = (const float*)d_in[22];
    const float* Wsrc2 = (const float*)d_in[23];
    const float* bsrc2 = (const float*)d_in[24];
    const float* Wdst2 = (const float*)d_in[25];
    const float* bdst2 = (const float*)d_in[26];
    const float* Wupd2 = (const float*)d_in[27];
    const float* bupd2 = (const float*)d_in[28];
    const float* bn_g = (const float*)d_in[29];
    const float* bn_b = (const float*)d_in[30];
    float* out = (float*)d_out;

    float* aggr0 = symf(g_aggr0);
    float* aggr1 = symf(g_aggr1);
    float* aggr2 = symf(g_aggr2);
    float* hA = symf(g_hA);
    float* hB = symf(g_hB);
    float* preA = symf(g_preA);
    float* preB = symf(g_preB);
    float* xAt = symf(g_xAt);
    float* xBt = symf(g_xBt);
    int* icnt = symi(g_icnt);
    int* roff = symi(g_roff);
    int* csr = symi(g_csr);
    float* WA1 = symf(g_WA1);
    float* WB1 = symf(g_WB1);
    float* WA2 = symf(g_WA2);
    float* WB2 = symf(g_WB2);
    float* bA1 = symf(g_bA1);
    float* bB1 = symf(g_bB1);
    float* bA2 = symf(g_bA2);
    float* bB2 = symf(g_bB2);
    float* part = symf(g_part);
    float* sc = symf(g_sc);
    float* sh = symf(g_sh);

    int* icnt_ab = icnt;          int* icnt_ba = icnt + NN;          int* icnt_aa = icnt + 2 * NN;
    int* roff_ab = roff;          int* roff_ba = roff + (NN + 1);    int* roff_aa = roff + 2 * (NN + 1);
    int* csr_ab = csr;            int* csr_ba = csr + NE;            int* csr_aa = csr + 2 * NE;

    const int EB = (NE + 255) / 256;            // 3125
    const int G256 = (NN + 3) / 4;              // 12500 (gather256 / 256-dim elementwise)
    const int G128 = (NN + 7) / 8;              // 6250
    dim3 cw_blk(256);
    dim3 ggrid(2, (NN + 127) / 128);

    // ---- CSR build (icnt zeroed explicitly every call; scan resets it for fill reuse) ----
    zero_int_kernel<<<(3 * NN + 255) / 256, 256>>>(icnt, 3 * NN);            // idx0
    count_int_kernel<<<EB, 256>>>(e_ab + NE, icnt_ab, NE);                   // idx1
    scan_kernel<<<1, 1024>>>(icnt_ab, roff_ab);                              // idx2 (resets icnt_ab)
    fill_kernel<<<EB, 256>>>(e_ab, e_ab + NE, roff_ab, icnt_ab, csr_ab, NE); // idx3
    round_kernel<<<G256, 256>>>(x_A, xAt, NN * 64);                          // idx4
    gather256_kernel<<<G256, 256>>>(x_A, roff_ab, csr_ab, aggr0);            // idx5 (ncu target)

    count_int_kernel<<<EB, 256>>>(e_ba + NE, icnt_ba, NE);
    scan_kernel<<<1, 1024>>>(icnt_ba, roff_ba);
    fill_kernel<<<EB, 256>>>(e_ba, e_ba + NE, roff_ba, icnt_ba, csr_ba, NE);
    count_int_kernel<<<EB, 256>>>(e_aa + NE, icnt_aa, NE);
    scan_kernel<<<1, 1024>>>(icnt_aa, roff_aa);
    fill_kernel<<<EB, 256>>>(e_aa, e_aa + NE, roff_aa, icnt_aa, csr_aa, NE);
    gather128_kernel<<<G128, 256>>>(x_B, roff_ba, csr_ba, aggr1);
    gather256_kernel<<<G256, 256>>>(x_A, roff_aa, csr_aa, aggr2);
    round_kernel<<<G128, 256>>>(x_B, xBt, NN * 32);

    // ---- combined weights (outputs tf32-rounded) ----
    combine_w_kernel<<<dim3(8, 32), cw_blk>>>(ba_Wupd1, 512, 0,   ba_Wdst1, 256, 0.5f, 0.f, WA1, 640, 0);
    combine_w_kernel<<<dim3(8, 32), cw_blk>>>(aa_Wupd1, 512, 0,   aa_Wdst1, 256, 0.5f, 1.f, WA1, 640, 0);
    combine_w_kernel<<<dim3(4, 32), cw_blk>>>(ba_Wupd1, 512, 256, ba_Wsrc1, 128, 0.5f, 0.f, WA1, 640, 256);
    combine_w_kernel<<<dim3(8, 32), cw_blk>>>(aa_Wupd1, 512, 256, aa_Wsrc1, 256, 0.5f, 0.f, WA1, 640, 384);
    combine_b_kernel<<<1, 256>>>(ba_Wupd1, 512, ba_bsrc1, ba_bdst1, ba_bupd1, 0.5f, 0.f, bA1);
    combine_b_kernel<<<1, 256>>>(aa_Wupd1, 512, aa_bsrc1, aa_bdst1, aa_bupd1, 0.5f, 1.f, bA1);
    combine_w_kernel<<<dim3(4, 32), cw_blk>>>(ab_Wupd1, 512, 0,   ab_Wdst1, 128, 1.f, 0.f, WB1, 384, 0);
    combine_w_kernel<<<dim3(8, 32), cw_blk>>>(ab_Wupd1, 512, 256, ab_Wsrc1, 256, 1.f, 0.f, WB1, 384, 128);
    combine_b_kernel<<<1, 256>>>(ab_Wupd1, 512, ab_bsrc1, ab_bdst1, ab_bupd1, 1.f, 0.f, bB1);
    combine_w_kernel<<<dim3(8, 32), cw_blk>>>(Wupd2 + 1 * 131072, 512, 0,   Wdst2 + 1 * 65536, 256, 0.5f, 0.f, WA2, 768, 0);
    combine_w_kernel<<<dim3(8, 32), cw_blk>>>(Wupd2 + 2 * 131072, 512, 0,   Wdst2 + 2 * 65536, 256, 0.5f, 1.f, WA2, 768, 0);
    combine_w_kernel<<<dim3(8, 32), cw_blk>>>(Wupd2 + 1 * 131072, 512, 256, Wsrc2 + 1 * 65536, 256, 0.5f, 0.f, WA2, 768, 256);
    combine_w_kernel<<<dim3(8, 32), cw_blk>>>(Wupd2 + 2 * 131072, 512, 256, Wsrc2 + 2 * 65536, 256, 0.5f, 0.f, WA2, 768, 512);
    combine_b_kernel<<<1, 256>>>(Wupd2 + 1 * 131072, 512, bsrc2 + 256, bdst2 + 256, bupd2 + 256, 0.5f, 0.f, bA2);
    combine_b_kernel<<<1, 256>>>(Wupd2 + 2 * 131072, 512, bsrc2 + 512, bdst2 + 512, bupd2 + 512, 0.5f, 1.f, bA2);
    combine_w_kernel<<<dim3(8, 32), cw_blk>>>(Wupd2, 512, 0,   Wdst2, 256, 1.f, 0.f, WB2, 512, 0);
    combine_w_kernel<<<dim3(8, 32), cw_blk>>>(Wupd2, 512, 256, Wsrc2, 256, 1.f, 0.f, WB2, 512, 256);
    combine_b_kernel<<<1, 256>>>(Wupd2, 512, bsrc2, bdst2, bupd2, 1.f, 0.f, bB2);

    // ---- layer 1 GEMMs ----
    gemm_tf32_kernel<<<ggrid, 256>>>(xAt, 256, aggr1, 128, aggr2, 256, WA1, bA1, preA, NN);
    gemm_tf32_kernel<<<ggrid, 256>>>(xBt, 128, aggr0, 256, nullptr, 0, WB1, bB1, preB, NN);

    // ---- layer 1 BN + LeakyReLU (hA/hB tf32-rounded at store) ----
    stats_kernel<<<STATS_BLKS, 256>>>(preA, NN, part);
    bn_finalize_kernel<<<1, 256>>>(part, bn_g + 0, bn_b + 0, NN, sc, sh);
    bn_apply_kernel<<<G256, 256>>>(preA, sc, sh, hA, NN, 1);
    stats_kernel<<<STATS_BLKS, 256>>>(preB, NN, part);
    bn_finalize_kernel<<<1, 256>>>(part, bn_g + 256, bn_b + 256, NN, sc, sh);
    bn_apply_kernel<<<G256, 256>>>(preB, sc, sh, hB, NN, 1);

    // ---- layer 2 gathers ----
    gather256_kernel<<<G256, 256>>>(hA, roff_ab, csr_ab, aggr0);
    gather256_kernel<<<G256, 256>>>(hB, roff_ba, csr_ba, aggr1);
    gather256_kernel<<<G256, 256>>>(hA, roff_aa, csr_aa, aggr2);

    // ---- layer 2 GEMMs ----
    gemm_tf32_kernel<<<ggrid, 256>>>(hA, 256, aggr1, 256, aggr2, 256, WA2, bA2, preA, NN);
    gemm_tf32_kernel<<<ggrid, 256>>>(hB, 256, aggr0, 256, nullptr, 0, WB2, bB2, preB, NN);

    // ---- layer 2 BN + LeakyReLU -> d_out (outA then outB, fp32, no rounding) ----
    stats_kernel<<<STATS_BLKS, 256>>>(preA, NN, part);
    bn_finalize_kernel<<<1, 256>>>(part, bn_g + 512, bn_b + 512, NN, sc, sh);
    bn_apply_kernel<<<G256, 256>>>(preA, sc, sh, out, NN, 0);
    stats_kernel<<<STATS_BLKS, 256>>>(preB, NN, part);
    bn_finalize_kernel<<<1, 256>>>(part, bn_g + 768, bn_b + 768, NN, sc, sh);
    bn_apply_kernel<<<G256, 256>>>(preB, sc, sh, out + (size_t)NN * HD, NN, 0);
}

// round 10
// speedup vs baseline: 3.3807x; 1.2839x over previous
#include <cuda_runtime.h>
#include <math.h>
#include <stdint.h>

#define NN 50000
#define NE 800000
#define HD  256
#define EPS_BN 1e-5f
#define SLOPE_LR 0.01f
#define STATS_BLKS 250
#define APAD 44                       // floats per smem row: 176B = 16B-aligned, conflict-free
#define GEMM_BUF (2 * 128 * APAD)     // floats per double-buffer slot (A tile + B tile)
#define GEMM_SMEM (2 * GEMM_BUF * 4)  // bytes: 90112

// ---------------- scratch (__device__ globals; no allocation allowed) ----------------
__device__ float g_aggr0[(size_t)NN * HD];
__device__ float g_aggr1[(size_t)NN * HD];
__device__ float g_aggr2[(size_t)NN * HD];
__device__ float g_hA[(size_t)NN * HD];
__device__ float g_hB[(size_t)NN * HD];
__device__ float g_preA[(size_t)NN * HD];
__device__ float g_preB[(size_t)NN * HD];
__device__ float g_xAt[(size_t)NN * 256];
__device__ float g_xBt[(size_t)NN * 128];
__device__ int   g_icnt[3 * NN];             // degree counts, then reused as fill cursors
__device__ int   g_roff[3 * (NN + 1)];
__device__ int   g_csr[3 * NE];
__device__ float g_WA1[HD * 640];
__device__ float g_WB1[HD * 384];
__device__ float g_WA2[HD * 768];
__device__ float g_WB2[HD * 512];
__device__ float g_bA1[HD], g_bB1[HD], g_bA2[HD], g_bB2[HD];
__device__ float g_partA[STATS_BLKS * 512];
__device__ float g_partB[STATS_BLKS * 512];
__device__ float g_scA[HD], g_shA[HD], g_scB[HD], g_shB[HD];

// ---------------- utility ----------------
__device__ __forceinline__ float to_tf32(float x) {
    uint32_t u;
    asm("cvt.rna.tf32.f32 %0, %1;" : "=r"(u) : "f"(x));
    return __uint_as_float(u);
}

__device__ __forceinline__ void cp16(uint32_t dst, const void* src, int srcsize) {
    asm volatile("cp.async.ca.shared.global [%0], [%1], 16, %2;"
                 :: "r"(dst), "l"(src), "r"(srcsize));
}

__global__ void zero_int_kernel(int* __restrict__ p, int n) {
    int i = blockIdx.x * blockDim.x + threadIdx.x;
    if (i < n) p[i] = 0;
}

__global__ void count_int_kernel(const int* __restrict__ dst, int* __restrict__ cnt, int E) {
    int e = blockIdx.x * blockDim.x + threadIdx.x;
    if (e < E) atomicAdd(cnt + dst[e], 1);
}

// single-block exclusive scan of NN ints -> roff[NN+1]; resets cnt for fill reuse
__global__ void scan_kernel(int* __restrict__ cnt, int* __restrict__ roff) {
    __shared__ int sm[1024];
    __shared__ int carry_s;
    int tid = threadIdx.x;
    if (tid == 0) { carry_s = 0; roff[0] = 0; }
    __syncthreads();
    for (int base = 0; base < NN; base += 1024) {
        int i = base + tid;
        int v = (i < NN) ? cnt[i] : 0;
        sm[tid] = v;
        __syncthreads();
#pragma unroll
        for (int off = 1; off < 1024; off <<= 1) {
            int t = (tid >= off) ? sm[tid - off] : 0;
            __syncthreads();
            sm[tid] += t;
            __syncthreads();
        }
        if (i < NN) {
            roff[i + 1] = carry_s + sm[tid];
            cnt[i] = 0;
        }
        __syncthreads();
        if (tid == 0) carry_s += sm[1023];
        __syncthreads();
    }
}

__global__ void fill_kernel(const int* __restrict__ src, const int* __restrict__ dst,
                            const int* __restrict__ roff, int* __restrict__ fill,
                            int* __restrict__ csr, int E) {
    int e = blockIdx.x * blockDim.x + threadIdx.x;
    if (e >= E) return;
    int d = dst[e];
    int pos = roff[d] + atomicAdd(fill + d, 1);
    csr[pos] = src[e];
}

// gather-mean over CSR, 256-dim rows: 4 nodes / 256-thread block, tf32-rounded output
__global__ void gather256_kernel(const float* __restrict__ feat,
                                 const int* __restrict__ roff,
                                 const int* __restrict__ csr,
                                 float* __restrict__ out) {
    int node = blockIdx.x * 4 + (threadIdx.x >> 6);
    int lane = threadIdx.x & 63;
    if (node >= NN) return;
    int j0 = roff[node], j1 = roff[node + 1];
    const float4* f = reinterpret_cast<const float4*>(feat);
    float4 acc = make_float4(0.f, 0.f, 0.f, 0.f);
    int j = j0;
    for (; j + 1 < j1; j += 2) {
        int s0 = csr[j], s1 = csr[j + 1];
        float4 a = f[(size_t)s0 * 64 + lane];
        float4 b = f[(size_t)s1 * 64 + lane];
        acc.x += a.x; acc.y += a.y; acc.z += a.z; acc.w += a.w;
        acc.x += b.x; acc.y += b.y; acc.z += b.z; acc.w += b.w;
    }
    if (j < j1) {
        int s = csr[j];
        float4 a = f[(size_t)s * 64 + lane];
        acc.x += a.x; acc.y += a.y; acc.z += a.z; acc.w += a.w;
    }
    float r = 1.0f / (float)max(j1 - j0, 1);
    float4 o;
    o.x = to_tf32(acc.x * r); o.y = to_tf32(acc.y * r);
    o.z = to_tf32(acc.z * r); o.w = to_tf32(acc.w * r);
    reinterpret_cast<float4*>(out)[(size_t)node * 64 + lane] = o;
}

// gather-mean, 128-dim rows
__global__ void gather128_kernel(const float* __restrict__ feat,
                                 const int* __restrict__ roff,
                                 const int* __restrict__ csr,
                                 float* __restrict__ out) {
    int node = blockIdx.x * 8 + (threadIdx.x >> 5);
    int lane = threadIdx.x & 31;
    if (node >= NN) return;
    int j0 = roff[node], j1 = roff[node + 1];
    const float4* f = reinterpret_cast<const float4*>(feat);
    float4 acc = make_float4(0.f, 0.f, 0.f, 0.f);
    int j = j0;
    for (; j + 1 < j1; j += 2) {
        int s0 = csr[j], s1 = csr[j + 1];
        float4 a = f[(size_t)s0 * 32 + lane];
        float4 b = f[(size_t)s1 * 32 + lane];
        acc.x += a.x; acc.y += a.y; acc.z += a.z; acc.w += a.w;
        acc.x += b.x; acc.y += b.y; acc.z += b.z; acc.w += b.w;
    }
    if (j < j1) {
        int s = csr[j];
        float4 a = f[(size_t)s * 32 + lane];
        acc.x += a.x; acc.y += a.y; acc.z += a.z; acc.w += a.w;
    }
    float r = 1.0f / (float)max(j1 - j0, 1);
    float4 o;
    o.x = to_tf32(acc.x * r); o.y = to_tf32(acc.y * r);
    o.z = to_tf32(acc.z * r); o.w = to_tf32(acc.w * r);
    reinterpret_cast<float4*>(out)[(size_t)node * 32 + lane] = o;
}

__global__ void round_kernel(const float* __restrict__ in, float* __restrict__ out, int n4) {
    int i = blockIdx.x * blockDim.x + threadIdx.x;
    if (i >= n4) return;
    float4 v = reinterpret_cast<const float4*>(in)[i];
    float4 o;
    o.x = to_tf32(v.x); o.y = to_tf32(v.y); o.z = to_tf32(v.z); o.w = to_tf32(v.w);
    reinterpret_cast<float4*>(out)[i] = o;
}

__global__ void combine_w_kernel(const float* __restrict__ Wupd, int wstride, int coff,
                                 const float* __restrict__ Ws, int d,
                                 float scale, float beta,
                                 float* __restrict__ out, int ostride, int ocoff) {
    int j = blockIdx.x * 32 + (threadIdx.x & 31);
    int o = blockIdx.y * 8 + (threadIdx.x >> 5);
    if (j >= d) return;
    float acc = 0.f;
    const float* wrow = Wupd + (size_t)o * wstride + coff;
#pragma unroll 4
    for (int i = 0; i < HD; i++)
        acc = fmaf(wrow[i], Ws[(size_t)i * d + j], acc);
    float* op = out + (size_t)o * ostride + ocoff + j;
    *op = to_tf32(beta * (*op) + scale * acc);
}

__global__ void combine_b_kernel(const float* __restrict__ Wupd, int wstride,
                                 const float* __restrict__ bsrc,
                                 const float* __restrict__ bdst,
                                 const float* __restrict__ bupd,
                                 float scale, float beta, float* __restrict__ out) {
    int o = threadIdx.x;
    float acc = bupd[o];
    const float* wrow = Wupd + (size_t)o * wstride;
#pragma unroll 4
    for (int i = 0; i < HD; i++)
        acc += wrow[i] * bdst[i] + wrow[HD + i] * bsrc[i];
    out[o] = beta * out[o] + scale * acc;
}

// ---------------- TF32 tensor-core GEMM, cp.async double-buffered ----------------
// C[M,256] = [A0|A1|A2] @ W^T + bias. Tile 128x128x32, one barrier per K-slab.
__global__ __launch_bounds__(256, 2) void gemm_tf32_kernel(
    const float* __restrict__ A0, int K0,
    const float* __restrict__ A1, int K1,
    const float* __restrict__ A2, int K2,
    const float* __restrict__ W, const float* __restrict__ bias,
    float* __restrict__ C, int M) {
    extern __shared__ float sm_[];
    const int Ktot = K0 + K1 + K2;
    int tid = threadIdx.x;
    int m0 = blockIdx.y * 128;
    int n0 = blockIdx.x * 128;
    int warp = tid >> 5, lane = tid & 31;
    int wm = (warp & 3) * 32;
    int wn = (warp >> 2) * 64;
    int lr = lane >> 2;
    int lc = lane & 3;
    uint32_t sbase = (uint32_t)__cvta_generic_to_shared(sm_);

    float acc[2][8][4];
#pragma unroll
    for (int mt = 0; mt < 2; mt++)
#pragma unroll
        for (int nt = 0; nt < 8; nt++)
#pragma unroll
            for (int q = 0; q < 4; q++) acc[mt][nt][q] = 0.f;

    auto issue = [&](int kb, int b) {
        const float* Ap; int sw, kl;
        if (kb < K0)           { Ap = A0; sw = K0; kl = kb; }
        else if (kb < K0 + K1) { Ap = A1; sw = K1; kl = kb - K0; }
        else                   { Ap = A2; sw = K2; kl = kb - K0 - K1; }
        uint32_t bb = sbase + b * (GEMM_BUF * 4);
#pragma unroll
        for (int q = 0; q < 4; q++) {
            int s = tid + q * 256;
            int m = s >> 3;
            int kq = s & 7;
            int gm = m0 + m;
            cp16(bb + (m * APAD + kq * 4) * 4,
                 Ap + (size_t)gm * sw + kl + kq * 4, gm < M ? 16 : 0);
            cp16(bb + (128 * APAD + m * APAD + kq * 4) * 4,
                 W + (size_t)(n0 + m) * Ktot + kb + kq * 4, 16);
        }
        asm volatile("cp.async.commit_group;");
    };

    int nslab = Ktot / 32;
    issue(0, 0);
    for (int is = 0; is < nslab; is++) {
        asm volatile("cp.async.wait_group 0;");
        __syncthreads();
        if (is + 1 < nslab) issue((is + 1) * 32, (is + 1) & 1);
        const float* As = sm_ + (is & 1) * GEMM_BUF;
        const float* Bs = As + 128 * APAD;

#pragma unroll
        for (int ks = 0; ks < 4; ks++) {
            int k0 = ks * 8;
            uint32_t af[2][4];
#pragma unroll
            for (int mt = 0; mt < 2; mt++) {
                int row = wm + mt * 16 + lr;
                af[mt][0] = __float_as_uint(As[row * APAD + k0 + lc]);
                af[mt][1] = __float_as_uint(As[(row + 8) * APAD + k0 + lc]);
                af[mt][2] = __float_as_uint(As[row * APAD + k0 + 4 + lc]);
                af[mt][3] = __float_as_uint(As[(row + 8) * APAD + k0 + 4 + lc]);
            }
#pragma unroll
            for (int nt = 0; nt < 8; nt++) {
                int col = wn + nt * 8 + lr;
                uint32_t b0 = __float_as_uint(Bs[col * APAD + k0 + lc]);
                uint32_t b1 = __float_as_uint(Bs[col * APAD + k0 + 4 + lc]);
#pragma unroll
                for (int mt = 0; mt < 2; mt++) {
                    asm volatile(
                        "mma.sync.aligned.m16n8k8.row.col.f32.tf32.tf32.f32 "
                        "{%0,%1,%2,%3}, {%4,%5,%6,%7}, {%8,%9}, {%0,%1,%2,%3};"
                        : "+f"(acc[mt][nt][0]), "+f"(acc[mt][nt][1]),
                          "+f"(acc[mt][nt][2]), "+f"(acc[mt][nt][3])
                        : "r"(af[mt][0]), "r"(af[mt][1]), "r"(af[mt][2]), "r"(af[mt][3]),
                          "r"(b0), "r"(b1));
                }
            }
        }
    }

#pragma unroll
    for (int mt = 0; mt < 2; mt++) {
#pragma unroll
        for (int nt = 0; nt < 8; nt++) {
            int gn = n0 + wn + nt * 8 + lc * 2;
            int gm = m0 + wm + mt * 16 + lr;
            float b0 = bias[gn], b1 = bias[gn + 1];
            if (gm < M) {
                float2 o = make_float2(acc[mt][nt][0] + b0, acc[mt][nt][1] + b1);
                *reinterpret_cast<float2*>(C + (size_t)gm * 256 + gn) = o;
            }
            if (gm + 8 < M) {
                float2 o = make_float2(acc[mt][nt][2] + b0, acc[mt][nt][3] + b1);
                *reinterpret_cast<float2*>(C + (size_t)(gm + 8) * 256 + gn) = o;
            }
        }
    }
}

// column-wise sum / sumsq partials (deterministic, no atomics)
__global__ void stats_kernel(const float* __restrict__ X, int M, float* __restrict__ part) {
    int t = threadIdx.x;
    int rows_per = (M + gridDim.x - 1) / gridDim.x;
    int r0 = blockIdx.x * rows_per;
    int r1 = min(r0 + rows_per, M);
    float a = 0.f, b = 0.f;
    for (int r = r0; r < r1; r++) {
        float v = X[(size_t)r * 256 + t];
        a += v;
        b += v * v;
    }
    part[blockIdx.x * 512 + t] = a;
    part[blockIdx.x * 512 + 256 + t] = b;
}

__global__ void bn_finalize_kernel(const float* __restrict__ part,
                                   const float* __restrict__ g, const float* __restrict__ bb,
                                   int M, float* __restrict__ sc, float* __restrict__ sh) {
    int t = threadIdx.x;
    float s = 0.f, s2 = 0.f;
    for (int blk = 0; blk < STATS_BLKS; blk++) {
        s += part[blk * 512 + t];
        s2 += part[blk * 512 + 256 + t];
    }
    float mean = s / (float)M;
    float var = s2 / (float)M - mean * mean;
    float a = g[t] * rsqrtf(var + EPS_BN);
    sc[t] = a;
    sh[t] = bb[t] - mean * a;
}

__global__ void bn_apply_kernel(const float* __restrict__ X,
                                const float* __restrict__ sc, const float* __restrict__ sh,
                                float* __restrict__ Y, int M, int do_round) {
    int i = blockIdx.x * blockDim.x + threadIdx.x;
    if (i >= M * 64) return;
    int c4 = i & 63;
    float4 a = reinterpret_cast<const float4*>(sc)[c4];
    float4 c = reinterpret_cast<const float4*>(sh)[c4];
    float4 x = reinterpret_cast<const float4*>(X)[i];
    float4 y;
    y.x = a.x * x.x + c.x; y.x = y.x > 0.f ? y.x : SLOPE_LR * y.x;
    y.y = a.y * x.y + c.y; y.y = y.y > 0.f ? y.y : SLOPE_LR * y.y;
    y.z = a.z * x.z + c.z; y.z = y.z > 0.f ? y.z : SLOPE_LR * y.z;
    y.w = a.w * x.w + c.w; y.w = y.w > 0.f ? y.w : SLOPE_LR * y.w;
    if (do_round) {
        y.x = to_tf32(y.x); y.y = to_tf32(y.y); y.z = to_tf32(y.z); y.w = to_tf32(y.w);
    }
    reinterpret_cast<float4*>(Y)[i] = y;
}

// ---------------- host orchestration ----------------
static inline float* symf(const void* s) {
    void* p = nullptr;
    cudaGetSymbolAddress(&p, s);
    return (float*)p;
}
static inline int* symi(const void* s) {
    void* p = nullptr;
    cudaGetSymbolAddress(&p, s);
    return (int*)p;
}

extern "C" void kernel_launch(void* const* d_in, const int* in_sizes, int n_in,
                              void* d_out, int out_size) {
    (void)in_sizes; (void)n_in; (void)out_size;
    const float* x_A = (const float*)d_in[0];
    const float* x_B = (const float*)d_in[1];
    const int* e_ab = (const int*)d_in[2];
    const int* e_ba = (const int*)d_in[3];
    const int* e_aa = (const int*)d_in[4];
    const float* ab_Wsrc1 = (const float*)d_in[5];
    const float* ab_bsrc1 = (const float*)d_in[6];
    const float* ab_Wdst1 = (const float*)d_in[7];
    const float* ab_bdst1 = (const float*)d_in[8];
    const float* ab_Wupd1 = (const float*)d_in[9];
    const float* ab_bupd1 = (const float*)d_in[10];
    const float* ba_Wsrc1 = (const float*)d_in[11];
    const float* ba_bsrc1 = (const float*)d_in[12];
    const float* ba_Wdst1 = (const float*)d_in[13];
    const float* ba_bdst1 = (const float*)d_in[14];
    const float* ba_Wupd1 = (const float*)d_in[15];
    const float* ba_bupd1 = (const float*)d_in[16];
    const float* aa_Wsrc1 = (const float*)d_in[17];
    const float* aa_bsrc1 = (const float*)d_in[18];
    const float* aa_Wdst1 = (const float*)d_in[19];
    const float* aa_bdst1 = (const float*)d_in[20];
    const float* aa_Wupd1 = (const float*)d_in[21];
    const float* aa_bupd1 = (const float*)d_in[22];
    const float* Wsrc2 = (const float*)d_in[23];
    const float* bsrc2 = (const float*)d_in[24];
    const float* Wdst2 = (const float*)d_in[25];
    const float* bdst2 = (const float*)d_in[26];
    const float* Wupd2 = (const float*)d_in[27];
    const float* bupd2 = (const float*)d_in[28];
    const float* bn_g = (const float*)d_in[29];
    const float* bn_b = (const float*)d_in[30];
    float* out = (float*)d_out;

    float* aggr0 = symf(g_aggr0);
    float* aggr1 = symf(g_aggr1);
    float* aggr2 = symf(g_aggr2);
    float* hA = symf(g_hA);
    float* hB = symf(g_hB);
    float* preA = symf(g_preA);
    float* preB = symf(g_preB);
    float* xAt = symf(g_xAt);
    float* xBt = symf(g_xBt);
    int* icnt = symi(g_icnt);
    int* roff = symi(g_roff);
    int* csr = symi(g_csr);
    float* WA1 = symf(g_WA1);
    float* WB1 = symf(g_WB1);
    float* WA2 = symf(g_WA2);
    float* WB2 = symf(g_WB2);
    float* bA1 = symf(g_bA1);
    float* bB1 = symf(g_bB1);
    float* bA2 = symf(g_bA2);
    float* bB2 = symf(g_bB2);
    float* partA = symf(g_partA);
    float* partB = symf(g_partB);
    float* scA = symf(g_scA);
    float* shA = symf(g_shA);
    float* scB = symf(g_scB);
    float* shB = symf(g_shB);

    int* icnt_ab = icnt;          int* icnt_ba = icnt + NN;          int* icnt_aa = icnt + 2 * NN;
    int* roff_ab = roff;          int* roff_ba = roff + (NN + 1);    int* roff_aa = roff + 2 * (NN + 1);
    int* csr_ab = csr;            int* csr_ba = csr + NE;            int* csr_aa = csr + 2 * NE;

    const int EB = (NE + 255) / 256;
    const int G256 = (NN + 3) / 4;
    const int G128 = (NN + 7) / 8;
    dim3 cw_blk(256);
    dim3 ggrid(2, (NN + 127) / 128);

    // one-time resources (created on the uncaptured correctness call; identical work every call)
    static cudaStream_t sW = nullptr, sB = nullptr, sC = nullptr;  // combines / ba-B-side / aa-aux
    static cudaEvent_t evZero, evW, evAb, evBa, evAa, evHA, evG0, evG1, evDone;
    static bool inited = false;
    if (!inited) {
        inited = true;
        cudaStreamCreateWithFlags(&sW, cudaStreamNonBlocking);
        cudaStreamCreateWithFlags(&sB, cudaStreamNonBlocking);
        cudaStreamCreateWithFlags(&sC, cudaStreamNonBlocking);
        cudaEventCreateWithFlags(&evZero, cudaEventDisableTiming);
        cudaEventCreateWithFlags(&evW, cudaEventDisableTiming);
        cudaEventCreateWithFlags(&evAb, cudaEventDisableTiming);
        cudaEventCreateWithFlags(&evBa, cudaEventDisableTiming);
        cudaEventCreateWithFlags(&evAa, cudaEventDisableTiming);
        cudaEventCreateWithFlags(&evHA, cudaEventDisableTiming);
        cudaEventCreateWithFlags(&evG0, cudaEventDisableTiming);
        cudaEventCreateWithFlags(&evG1, cudaEventDisableTiming);
        cudaEventCreateWithFlags(&evDone, cudaEventDisableTiming);
        cudaFuncSetAttribute(gemm_tf32_kernel,
                             cudaFuncAttributeMaxDynamicSharedMemorySize, GEMM_SMEM);
    }

    // ---- fork: zero degree counters, then 3 CSR chains + combines in parallel ----
    zero_int_kernel<<<(3 * NN + 255) / 256, 256>>>(icnt, 3 * NN);
    cudaEventRecord(evZero, 0);
    cudaStreamWaitEvent(sW, evZero, 0);
    cudaStreamWaitEvent(sB, evZero, 0);
    cudaStreamWaitEvent(sC, evZero, 0);

    // stream sW: weight combines + input rounding (independent of edges)
    round_kernel<<<G256, 256, 0, sW>>>(x_A, xAt, NN * 64);
    round_kernel<<<G128, 256, 0, sW>>>(x_B, xBt, NN * 32);
    combine_w_kernel<<<dim3(8, 32), cw_blk, 0, sW>>>(ba_Wupd1, 512, 0,   ba_Wdst1, 256, 0.5f, 0.f, WA1, 640, 0);
    combine_w_kernel<<<dim3(8, 32), cw_blk, 0, sW>>>(aa_Wupd1, 512, 0,   aa_Wdst1, 256, 0.5f, 1.f, WA1, 640, 0);
    combine_w_kernel<<<dim3(4, 32), cw_blk, 0, sW>>>(ba_Wupd1, 512, 256, ba_Wsrc1, 128, 0.5f, 0.f, WA1, 640, 256);
    combine_w_kernel<<<dim3(8, 32), cw_blk, 0, sW>>>(aa_Wupd1, 512, 256, aa_Wsrc1, 256, 0.5f, 0.f, WA1, 640, 384);
    combine_b_kernel<<<1, 256, 0, sW>>>(ba_Wupd1, 512, ba_bsrc1, ba_bdst1, ba_bupd1, 0.5f, 0.f, bA1);
    combine_b_kernel<<<1, 256, 0, sW>>>(aa_Wupd1, 512, aa_bsrc1, aa_bdst1, aa_bupd1, 0.5f, 1.f, bA1);
    combine_w_kernel<<<dim3(4, 32), cw_blk, 0, sW>>>(ab_Wupd1, 512, 0,   ab_Wdst1, 128, 1.f, 0.f, WB1, 384, 0);
    combine_w_kernel<<<dim3(8, 32), cw_blk, 0, sW>>>(ab_Wupd1, 512, 256, ab_Wsrc1, 256, 1.f, 0.f, WB1, 384, 128);
    combine_b_kernel<<<1, 256, 0, sW>>>(ab_Wupd1, 512, ab_bsrc1, ab_bdst1, ab_bupd1, 1.f, 0.f, bB1);
    combine_w_kernel<<<dim3(8, 32), cw_blk, 0, sW>>>(Wupd2 + 1 * 131072, 512, 0,   Wdst2 + 1 * 65536, 256, 0.5f, 0.f, WA2, 768, 0);
    combine_w_kernel<<<dim3(8, 32), cw_blk, 0, sW>>>(Wupd2 + 2 * 131072, 512, 0,   Wdst2 + 2 * 65536, 256, 0.5f, 1.f, WA2, 768, 0);
    combine_w_kernel<<<dim3(8, 32), cw_blk, 0, sW>>>(Wupd2 + 1 * 131072, 512, 256, Wsrc2 + 1 * 65536, 256, 0.5f, 0.f, WA2, 768, 256);
    combine_w_kernel<<<dim3(8, 32), cw_blk, 0, sW>>>(Wupd2 + 2 * 131072, 512, 256, Wsrc2 + 2 * 65536, 256, 0.5f, 0.f, WA2, 768, 512);
    combine_b_kernel<<<1, 256, 0, sW>>>(Wupd2 + 1 * 131072, 512, bsrc2 + 256, bdst2 + 256, bupd2 + 256, 0.5f, 0.f, bA2);
    combine_b_kernel<<<1, 256, 0, sW>>>(Wupd2 + 2 * 131072, 512, bsrc2 + 512, bdst2 + 512, bupd2 + 512, 0.5f, 1.f, bA2);
    combine_w_kernel<<<dim3(8, 32), cw_blk, 0, sW>>>(Wupd2, 512, 0,   Wdst2, 256, 1.f, 0.f, WB2, 512, 0);
    combine_w_kernel<<<dim3(8, 32), cw_blk, 0, sW>>>(Wupd2, 512, 256, Wsrc2, 256, 1.f, 0.f, WB2, 512, 256);
    combine_b_kernel<<<1, 256, 0, sW>>>(Wupd2, 512, bsrc2, bdst2, bupd2, 1.f, 0.f, bB2);
    cudaEventRecord(evW, sW);

    // stream sB: ba chain
    count_int_kernel<<<EB, 256, 0, sB>>>(e_ba + NE, icnt_ba, NE);
    scan_kernel<<<1, 1024, 0, sB>>>(icnt_ba, roff_ba);
    fill_kernel<<<EB, 256, 0, sB>>>(e_ba, e_ba + NE, roff_ba, icnt_ba, csr_ba, NE);
    gather128_kernel<<<G128, 256, 0, sB>>>(x_B, roff_ba, csr_ba, aggr1);
    cudaEventRecord(evBa, sB);

    // stream sC: aa chain
    count_int_kernel<<<EB, 256, 0, sC>>>(e_aa + NE, icnt_aa, NE);
    scan_kernel<<<1, 1024, 0, sC>>>(icnt_aa, roff_aa);
    fill_kernel<<<EB, 256, 0, sC>>>(e_aa, e_aa + NE, roff_aa, icnt_aa, csr_aa, NE);
    gather256_kernel<<<G256, 256, 0, sC>>>(x_A, roff_aa, csr_aa, aggr2);
    cudaEventRecord(evAa, sC);

    // default stream: ab chain
    count_int_kernel<<<EB, 256>>>(e_ab + NE, icnt_ab, NE);
    scan_kernel<<<1, 1024>>>(icnt_ab, roff_ab);
    fill_kernel<<<EB, 256>>>(e_ab, e_ab + NE, roff_ab, icnt_ab, csr_ab, NE);
    gather256_kernel<<<G256, 256>>>(x_A, roff_ab, csr_ab, aggr0);
    cudaEventRecord(evAb, 0);

    // ---- layer 1 GEMM A + BN (default stream), GEMM B + BN (sB) concurrently ----
    cudaStreamWaitEvent(0, evW, 0);
    cudaStreamWaitEvent(0, evBa, 0);
    cudaStreamWaitEvent(0, evAa, 0);
    gemm_tf32_kernel<<<ggrid, 256, GEMM_SMEM>>>(xAt, 256, aggr1, 128, aggr2, 256, WA1, bA1, preA, NN);
    stats_kernel<<<STATS_BLKS, 256>>>(preA, NN, partA);
    bn_finalize_kernel<<<1, 256>>>(partA, bn_g + 0, bn_b + 0, NN, scA, shA);
    bn_apply_kernel<<<G256, 256>>>(preA, scA, shA, hA, NN, 1);
    cudaEventRecord(evHA, 0);

    cudaStreamWaitEvent(sB, evAb, 0);
    cudaStreamWaitEvent(sB, evW, 0);
    gemm_tf32_kernel<<<ggrid, 256, GEMM_SMEM, sB>>>(xBt, 128, aggr0, 256, nullptr, 0, WB1, bB1, preB, NN);
    stats_kernel<<<STATS_BLKS, 256, 0, sB>>>(preB, NN, partB);
    bn_finalize_kernel<<<1, 256, 0, sB>>>(partB, bn_g + 256, bn_b + 256, NN, scB, shB);
    bn_apply_kernel<<<G256, 256, 0, sB>>>(preB, scB, shB, hB, NN, 1);
    // layer 2 ba gather (hB and csr_ba both live on sB)
    gather256_kernel<<<G256, 256, 0, sB>>>(hB, roff_ba, csr_ba, aggr1);
    cudaEventRecord(evG1, sB);

    // stream sC: layer 2 ab gather (needs hA; csr_ab ordered via evHA's stream history)
    cudaStreamWaitEvent(sC, evHA, 0);
    gather256_kernel<<<G256, 256, 0, sC>>>(hA, roff_ab, csr_ab, aggr0);
    cudaEventRecord(evG0, sC);

    // default stream: layer 2 aa gather (csr_aa ordered via evAa wait above)
    gather256_kernel<<<G256, 256>>>(hA, roff_aa, csr_aa, aggr2);

    // ---- layer 2 GEMM A + BN (default), GEMM B + BN (sB) ----
    cudaStreamWaitEvent(0, evG1, 0);
    gemm_tf32_kernel<<<ggrid, 256, GEMM_SMEM>>>(hA, 256, aggr1, 256, aggr2, 256, WA2, bA2, preA, NN);
    stats_kernel<<<STATS_BLKS, 256>>>(preA, NN, partA);
    bn_finalize_kernel<<<1, 256>>>(partA, bn_g + 512, bn_b + 512, NN, scA, shA);
    bn_apply_kernel<<<G256, 256>>>(preA, scA, shA, out, NN, 0);

    cudaStreamWaitEvent(sB, evG0, 0);
    gemm_tf32_kernel<<<ggrid, 256, GEMM_SMEM, sB>>>(hB, 256, aggr0, 256, nullptr, 0, WB2, bB2, preB, NN);
    stats_kernel<<<STATS_BLKS, 256, 0, sB>>>(preB, NN, partB);
    bn_finalize_kernel<<<1, 256, 0, sB>>>(partB, bn_g + 768, bn_b + 768, NN, scB, shB);
    bn_apply_kernel<<<G256, 256, 0, sB>>>(preB, scB, shB, out + (size_t)NN * HD, NN, 0);
    cudaEventRecord(evDone, sB);

    // join everything back into the capture-origin stream
    cudaStreamWaitEvent(0, evDone, 0);
}

// round 16
// speedup vs baseline: 5.8287x; 1.7241x over previous
#include <cuda_runtime.h>
#include <math.h>
#include <stdint.h>

#define NN 50000
#define NE 800000
#define HD  256
#define EPS_BN 1e-5f
#define SLOPE_LR 0.01f
#define STATS_BLKS 250
#define APAD 44                       // floats per smem row: 176B = 16B-aligned, conflict-free
#define GEMM_BUF (2 * 128 * APAD)     // floats per double-buffer slot (A tile + B tile)
#define GEMM_SMEM (2 * GEMM_BUF * 4)  // bytes: 90112

// ---------------- scratch (__device__ globals; no allocation allowed) ----------------
__device__ float g_aggr0[(size_t)NN * HD];
__device__ float g_aggr1[(size_t)NN * HD];
__device__ float g_aggr2[(size_t)NN * HD];
__device__ float g_hA[(size_t)NN * HD];
__device__ float g_hB[(size_t)NN * HD];
__device__ float g_preA[(size_t)NN * HD];
__device__ float g_preB[(size_t)NN * HD];
__device__ float g_xAt[(size_t)NN * 256];
__device__ float g_xBt[(size_t)NN * 128];
__device__ int   g_icnt[3 * NN];             // degree counts, then reused as fill cursors
__device__ int   g_roff[3 * (NN + 1)];
__device__ int   g_csr[3 * NE];
__device__ float g_WA1[HD * 640];
__device__ float g_WB1[HD * 384];
__device__ float g_WA2[HD * 768];
__device__ float g_WB2[HD * 512];
__device__ float g_bA1[HD], g_bB1[HD], g_bA2[HD], g_bB2[HD];
__device__ float g_partA[STATS_BLKS * 512];
__device__ float g_partB[STATS_BLKS * 512];
__device__ float g_scA[HD], g_shA[HD], g_scB[HD], g_shB[HD];

// ---------------- utility ----------------
__device__ __forceinline__ float to_tf32(float x) {
    uint32_t u;
    asm("cvt.rna.tf32.f32 %0, %1;" : "=r"(u) : "f"(x));
    return __uint_as_float(u);
}

__device__ __forceinline__ void cp16(uint32_t dst, const void* src, int srcsize) {
    asm volatile("cp.async.ca.shared.global [%0], [%1], 16, %2;"
                 :: "r"(dst), "l"(src), "r"(srcsize));
}

__global__ void zero_int_kernel(int* __restrict__ p, int n) {
    int i = blockIdx.x * blockDim.x + threadIdx.x;
    if (i < n) p[i] = 0;
}

__global__ void count_int_kernel(const int* __restrict__ dst, int* __restrict__ cnt, int E) {
    int e = blockIdx.x * blockDim.x + threadIdx.x;
    if (e < E) atomicAdd(cnt + dst[e], 1);
}

// chunked exclusive scan: 1024 threads, each owns a contiguous chunk; 2 barriers total.
// Also resets cnt to 0 for reuse as the fill cursor.
__global__ void scan_kernel(int* __restrict__ cnt, int* __restrict__ roff) {
    const int C = (NN + 1023) / 1024;     // 49
    int tid = threadIdx.x;
    int lane = tid & 31, wid = tid >> 5;
    int start = tid * C;
    int end = min(start + C, NN);
    int sum = 0;
    for (int i = start; i < end; i++) sum += cnt[i];

    // inclusive warp scan of chunk sums
    int v = sum;
#pragma unroll
    for (int off = 1; off < 32; off <<= 1) {
        int t = __shfl_up_sync(0xffffffffu, v, off);
        if (lane >= off) v += t;
    }
    __shared__ int wsum[32];
    if (lane == 31) wsum[wid] = v;
    __syncthreads();
    if (wid == 0) {
        int w = wsum[lane];
#pragma unroll
        for (int off = 1; off < 32; off <<= 1) {
            int t = __shfl_up_sync(0xffffffffu, w, off);
            if (lane >= off) w += t;
        }
        wsum[lane] = w;
    }
    __syncthreads();
    int excl = v - sum + (wid > 0 ? wsum[wid - 1] : 0);

    int run = excl;
    for (int i = start; i < end; i++) {
        run += cnt[i];
        roff[i + 1] = run;
        cnt[i] = 0;
    }
    if (tid == 0) roff[0] = 0;
}

__global__ void fill_kernel(const int* __restrict__ src, const int* __restrict__ dst,
                            const int* __restrict__ roff, int* __restrict__ fill,
                            int* __restrict__ csr, int E) {
    int e = blockIdx.x * blockDim.x + threadIdx.x;
    if (e >= E) return;
    int d = dst[e];
    int pos = roff[d] + atomicAdd(fill + d, 1);
    csr[pos] = src[e];
}

// gather-mean over CSR, 256-dim rows: 4 nodes / 256-thread block, tf32-rounded output
__global__ void gather256_kernel(const float* __restrict__ feat,
                                 const int* __restrict__ roff,
                                 const int* __restrict__ csr,
                                 float* __restrict__ out) {
    int node = blockIdx.x * 4 + (threadIdx.x >> 6);
    int lane = threadIdx.x & 63;
    if (node >= NN) return;
    int j0 = roff[node], j1 = roff[node + 1];
    const float4* f = reinterpret_cast<const float4*>(feat);
    float4 acc = make_float4(0.f, 0.f, 0.f, 0.f);
    int j = j0;
    for (; j + 1 < j1; j += 2) {
        int s0 = csr[j], s1 = csr[j + 1];
        float4 a = f[(size_t)s0 * 64 + lane];
        float4 b = f[(size_t)s1 * 64 + lane];
        acc.x += a.x; acc.y += a.y; acc.z += a.z; acc.w += a.w;
        acc.x += b.x; acc.y += b.y; acc.z += b.z; acc.w += b.w;
    }
    if (j < j1) {
        int s = csr[j];
        float4 a = f[(size_t)s * 64 + lane];
        acc.x += a.x; acc.y += a.y; acc.z += a.z; acc.w += a.w;
    }
    float r = 1.0f / (float)max(j1 - j0, 1);
    float4 o;
    o.x = to_tf32(acc.x * r); o.y = to_tf32(acc.y * r);
    o.z = to_tf32(acc.z * r); o.w = to_tf32(acc.w * r);
    reinterpret_cast<float4*>(out)[(size_t)node * 64 + lane] = o;
}

// gather-mean, 128-dim rows
__global__ void gather128_kernel(const float* __restrict__ feat,
                                 const int* __restrict__ roff,
                                 const int* __restrict__ csr,
                                 float* __restrict__ out) {
    int node = blockIdx.x * 8 + (threadIdx.x >> 5);
    int lane = threadIdx.x & 31;
    if (node >= NN) return;
    int j0 = roff[node], j1 = roff[node + 1];
    const float4* f = reinterpret_cast<const float4*>(feat);
    float4 acc = make_float4(0.f, 0.f, 0.f, 0.f);
    int j = j0;
    for (; j + 1 < j1; j += 2) {
        int s0 = csr[j], s1 = csr[j + 1];
        float4 a = f[(size_t)s0 * 32 + lane];
        float4 b = f[(size_t)s1 * 32 + lane];
        acc.x += a.x; acc.y += a.y; acc.z += a.z; acc.w += a.w;
        acc.x += b.x; acc.y += b.y; acc.z += b.z; acc.w += b.w;
    }
    if (j < j1) {
        int s = csr[j];
        float4 a = f[(size_t)s * 32 + lane];
        acc.x += a.x; acc.y += a.y; acc.z += a.z; acc.w += a.w;
    }
    float r = 1.0f / (float)max(j1 - j0, 1);
    float4 o;
    o.x = to_tf32(acc.x * r); o.y = to_tf32(acc.y * r);
    o.z = to_tf32(acc.z * r); o.w = to_tf32(acc.w * r);
    reinterpret_cast<float4*>(out)[(size_t)node * 32 + lane] = o;
}

__global__ void round_kernel(const float* __restrict__ in, float* __restrict__ out, int n4) {
    int i = blockIdx.x * blockDim.x + threadIdx.x;
    if (i >= n4) return;
    float4 v = reinterpret_cast<const float4*>(in)[i];
    float4 o;
    o.x = to_tf32(v.x); o.y = to_tf32(v.y); o.z = to_tf32(v.z); o.w = to_tf32(v.w);
    reinterpret_cast<float4*>(out)[i] = o;
}

// ---------------- batched weight combine ----------------
// Each descriptor: out[:, ocoff:ocoff+d] = tf32( scale * (A1@B1 [+ A2@B2]) )
// A: [256][astride] row-major slice; B: [256][d] row-major. One 64x64 tile per block.
struct WDesc {
    const float* A1; const float* B1;
    const float* A2; const float* B2;     // nullptr if single-term
    float* out;
    int astride, d, ostride, ocoff;
    float scale;
    int tile0;                            // first global tile index of this desc
};
struct WDescPack { WDesc w[10]; };

__global__ __launch_bounds__(256) void combine_w_batched(WDescPack p) {
    __shared__ float As[32][68];
    __shared__ float Bs[32][68];
    int bid = blockIdx.x;
    // find descriptor
    int di = 0;
#pragma unroll
    for (int i = 1; i < 10; i++)
        if (bid >= p.w[i].tile0) di = i;
    const WDesc w = p.w[di];
    int lt = bid - w.tile0;
    int ncols = w.d >> 6;                 // tiles along n
    int mtile = lt / ncols, ntile = lt % ncols;
    int m0 = mtile * 64, n0 = ntile * 64;

    int tid = threadIdx.x;
    int tx = tid & 15, ty = tid >> 4;

    float acc[4][4];
#pragma unroll
    for (int i = 0; i < 4; i++)
#pragma unroll
        for (int j = 0; j < 4; j++) acc[i][j] = 0.f;

    for (int term = 0; term < 2; term++) {
        const float* A = term ? w.A2 : w.A1;
        const float* B = term ? w.B2 : w.B1;
        if (!A) break;
        for (int kc = 0; kc < 256; kc += 32) {
            __syncthreads();
            // A chunk: 64 rows x 32 k, stored transposed As[k][m]
#pragma unroll
            for (int q = 0; q < 2; q++) {
                int s = tid + q * 256;
                int m = s >> 3, k4 = s & 7;
                float4 a = *reinterpret_cast<const float4*>(
                    A + (size_t)(m0 + m) * w.astride + kc + k4 * 4);
                As[k4 * 4 + 0][m] = a.x; As[k4 * 4 + 1][m] = a.y;
                As[k4 * 4 + 2][m] = a.z; As[k4 * 4 + 3][m] = a.w;
            }
            // B chunk: 32 k x 64 n, direct Bs[k][n]
#pragma unroll
            for (int q = 0; q < 2; q++) {
                int s = tid + q * 256;
                int k = s >> 4, n4 = s & 15;
                float4 b = *reinterpret_cast<const float4*>(
                    B + (size_t)(kc + k) * w.d + n0 + n4 * 4);
                *reinterpret_cast<float4*>(&Bs[k][n4 * 4]) = b;
            }
            __syncthreads();
#pragma unroll
            for (int k = 0; k < 32; k++) {
                float4 a = *reinterpret_cast<const float4*>(&As[k][ty * 4]);
                float4 b = *reinterpret_cast<const float4*>(&Bs[k][tx * 4]);
                float av[4] = {a.x, a.y, a.z, a.w};
                float bv[4] = {b.x, b.y, b.z, b.w};
#pragma unroll
                for (int i = 0; i < 4; i++)
#pragma unroll
                    for (int j = 0; j < 4; j++)
                        acc[i][j] = fmaf(av[i], bv[j], acc[i][j]);
            }
        }
    }

#pragma unroll
    for (int i = 0; i < 4; i++) {
        int o = m0 + ty * 4 + i;
#pragma unroll
        for (int j = 0; j < 4; j++)
            w.out[(size_t)o * w.ostride + w.ocoff + n0 + tx * 4 + j] =
                to_tf32(w.scale * acc[i][j]);
    }
}

// batched bias combine
struct BDesc {
    const float* W1; const float* bsrc1; const float* bdst1; const float* bupd1;
    const float* W2; const float* bsrc2; const float* bdst2; const float* bupd2;
    float* out; float scale;
};
struct BDescPack { BDesc b[4]; };

__global__ void combine_b_batched(BDescPack p) {
    const BDesc d = p.b[blockIdx.x];
    int o = threadIdx.x;
    float total = 0.f;
    {
        float acc = d.bupd1[o];
        const float* wrow = d.W1 + (size_t)o * 512;
#pragma unroll 4
        for (int i = 0; i < HD; i++)
            acc += wrow[i] * d.bdst1[i] + wrow[HD + i] * d.bsrc1[i];
        total += acc;
    }
    if (d.W2) {
        float acc = d.bupd2[o];
        const float* wrow = d.W2 + (size_t)o * 512;
#pragma unroll 4
        for (int i = 0; i < HD; i++)
            acc += wrow[i] * d.bdst2[i] + wrow[HD + i] * d.bsrc2[i];
        total += acc;
    }
    d.out[o] = d.scale * total;
}

// ---------------- TF32 tensor-core GEMM, cp.async double-buffered ----------------
__global__ __launch_bounds__(256, 2) void gemm_tf32_kernel(
    const float* __restrict__ A0, int K0,
    const float* __restrict__ A1, int K1,
    const float* __restrict__ A2, int K2,
    const float* __restrict__ W, const float* __restrict__ bias,
    float* __restrict__ C, int M) {
    extern __shared__ float sm_[];
    const int Ktot = K0 + K1 + K2;
    int tid = threadIdx.x;
    int m0 = blockIdx.y * 128;
    int n0 = blockIdx.x * 128;
    int warp = tid >> 5, lane = tid & 31;
    int wm = (warp & 3) * 32;
    int wn = (warp >> 2) * 64;
    int lr = lane >> 2;
    int lc = lane & 3;
    uint32_t sbase = (uint32_t)__cvta_generic_to_shared(sm_);

    float acc[2][8][4];
#pragma unroll
    for (int mt = 0; mt < 2; mt++)
#pragma unroll
        for (int nt = 0; nt < 8; nt++)
#pragma unroll
            for (int q = 0; q < 4; q++) acc[mt][nt][q] = 0.f;

    auto issue = [&](int kb, int b) {
        const float* Ap; int sw, kl;
        if (kb < K0)           { Ap = A0; sw = K0; kl = kb; }
        else if (kb < K0 + K1) { Ap = A1; sw = K1; kl = kb - K0; }
        else                   { Ap = A2; sw = K2; kl = kb - K0 - K1; }
        uint32_t bb = sbase + b * (GEMM_BUF * 4);
#pragma unroll
        for (int q = 0; q < 4; q++) {
            int s = tid + q * 256;
            int m = s >> 3;
            int kq = s & 7;
            int gm = m0 + m;
            cp16(bb + (m * APAD + kq * 4) * 4,
                 Ap + (size_t)gm * sw + kl + kq * 4, gm < M ? 16 : 0);
            cp16(bb + (128 * APAD + m * APAD + kq * 4) * 4,
                 W + (size_t)(n0 + m) * Ktot + kb + kq * 4, 16);
        }
        asm volatile("cp.async.commit_group;");
    };

    int nslab = Ktot / 32;
    issue(0, 0);
    for (int is = 0; is < nslab; is++) {
        asm volatile("cp.async.wait_group 0;");
        __syncthreads();
        if (is + 1 < nslab) issue((is + 1) * 32, (is + 1) & 1);
        const float* As = sm_ + (is & 1) * GEMM_BUF;
        const float* Bs = As + 128 * APAD;

#pragma unroll
        for (int ks = 0; ks < 4; ks++) {
            int k0 = ks * 8;
            uint32_t af[2][4];
#pragma unroll
            for (int mt = 0; mt < 2; mt++) {
                int row = wm + mt * 16 + lr;
                af[mt][0] = __float_as_uint(As[row * APAD + k0 + lc]);
                af[mt][1] = __float_as_uint(As[(row + 8) * APAD + k0 + lc]);
                af[mt][2] = __float_as_uint(As[row * APAD + k0 + 4 + lc]);
                af[mt][3] = __float_as_uint(As[(row + 8) * APAD + k0 + 4 + lc]);
            }
#pragma unroll
            for (int nt = 0; nt < 8; nt++) {
                int col = wn + nt * 8 + lr;
                uint32_t b0 = __float_as_uint(Bs[col * APAD + k0 + lc]);
                uint32_t b1 = __float_as_uint(Bs[col * APAD + k0 + 4 + lc]);
#pragma unroll
                for (int mt = 0; mt < 2; mt++) {
                    asm volatile(
                        "mma.sync.aligned.m16n8k8.row.col.f32.tf32.tf32.f32 "
                        "{%0,%1,%2,%3}, {%4,%5,%6,%7}, {%8,%9}, {%0,%1,%2,%3};"
                        : "+f"(acc[mt][nt][0]), "+f"(acc[mt][nt][1]),
                          "+f"(acc[mt][nt][2]), "+f"(acc[mt][nt][3])
                        : "r"(af[mt][0]), "r"(af[mt][1]), "r"(af[mt][2]), "r"(af[mt][3]),
                          "r"(b0), "r"(b1));
                }
            }
        }
    }

#pragma unroll
    for (int mt = 0; mt < 2; mt++) {
#pragma unroll
        for (int nt = 0; nt < 8; nt++) {
            int gn = n0 + wn + nt * 8 + lc * 2;
            int gm = m0 + wm + mt * 16 + lr;
            float b0 = bias[gn], b1 = bias[gn + 1];
            if (gm < M) {
                float2 o = make_float2(acc[mt][nt][0] + b0, acc[mt][nt][1] + b1);
                *reinterpret_cast<float2*>(C + (size_t)gm * 256 + gn) = o;
            }
            if (gm + 8 < M) {
                float2 o = make_float2(acc[mt][nt][2] + b0, acc[mt][nt][3] + b1);
                *reinterpret_cast<float2*>(C + (size_t)(gm + 8) * 256 + gn) = o;
            }
        }
    }
}

// column-wise sum / sumsq partials (deterministic, no atomics)
__global__ void stats_kernel(const float* __restrict__ X, int M, float* __restrict__ part) {
    int t = threadIdx.x;
    int rows_per = (M + gridDim.x - 1) / gridDim.x;
    int r0 = blockIdx.x * rows_per;
    int r1 = min(r0 + rows_per, M);
    float a = 0.f, b = 0.f;
    for (int r = r0; r < r1; r++) {
        float v = X[(size_t)r * 256 + t];
        a += v;
        b += v * v;
    }
    part[blockIdx.x * 512 + t] = a;
    part[blockIdx.x * 512 + 256 + t] = b;
}

__global__ void bn_finalize_kernel(const float* __restrict__ part,
                                   const float* __restrict__ g, const float* __restrict__ bb,
                                   int M, float* __restrict__ sc, float* __restrict__ sh) {
    int t = threadIdx.x;
    float s = 0.f, s2 = 0.f;
    for (int blk = 0; blk < STATS_BLKS; blk++) {
        s += part[blk * 512 + t];
        s2 += part[blk * 512 + 256 + t];
    }
    float mean = s / (float)M;
    float var = s2 / (float)M - mean * mean;
    float a = g[t] * rsqrtf(var + EPS_BN);
    sc[t] = a;
    sh[t] = bb[t] - mean * a;
}

__global__ void bn_apply_kernel(const float* __restrict__ X,
                                const float* __restrict__ sc, const float* __restrict__ sh,
                                float* __restrict__ Y, int M, int do_round) {
    int i = blockIdx.x * blockDim.x + threadIdx.x;
    if (i >= M * 64) return;
    int c4 = i & 63;
    float4 a = reinterpret_cast<const float4*>(sc)[c4];
    float4 c = reinterpret_cast<const float4*>(sh)[c4];
    float4 x = reinterpret_cast<const float4*>(X)[i];
    float4 y;
    y.x = a.x * x.x + c.x; y.x = y.x > 0.f ? y.x : SLOPE_LR * y.x;
    y.y = a.y * x.y + c.y; y.y = y.y > 0.f ? y.y : SLOPE_LR * y.y;
    y.z = a.z * x.z + c.z; y.z = y.z > 0.f ? y.z : SLOPE_LR * y.z;
    y.w = a.w * x.w + c.w; y.w = y.w > 0.f ? y.w : SLOPE_LR * y.w;
    if (do_round) {
        y.x = to_tf32(y.x); y.y = to_tf32(y.y); y.z = to_tf32(y.z); y.w = to_tf32(y.w);
    }
    reinterpret_cast<float4*>(Y)[i] = y;
}

// ---------------- host orchestration ----------------
static inline float* symf(const void* s) {
    void* p = nullptr;
    cudaGetSymbolAddress(&p, s);
    return (float*)p;
}
static inline int* symi(const void* s) {
    void* p = nullptr;
    cudaGetSymbolAddress(&p, s);
    return (int*)p;
}

extern "C" void kernel_launch(void* const* d_in, const int* in_sizes, int n_in,
                              void* d_out, int out_size) {
    (void)in_sizes; (void)n_in; (void)out_size;
    const float* x_A = (const float*)d_in[0];
    const float* x_B = (const float*)d_in[1];
    const int* e_ab = (const int*)d_in[2];
    const int* e_ba = (const int*)d_in[3];
    const int* e_aa = (const int*)d_in[4];
    const float* ab_Wsrc1 = (const float*)d_in[5];
    const float* ab_bsrc1 = (const float*)d_in[6];
    const float* ab_Wdst1 = (const float*)d_in[7];
    const float* ab_bdst1 = (const float*)d_in[8];
    const float* ab_Wupd1 = (const float*)d_in[9];
    const float* ab_bupd1 = (const float*)d_in[10];
    const float* ba_Wsrc1 = (const float*)d_in[11];
    const float* ba_bsrc1 = (const float*)d_in[12];
    const float* ba_Wdst1 = (const float*)d_in[13];
    const float* ba_bdst1 = (const float*)d_in[14];
    const float* ba_Wupd1 = (const float*)d_in[15];
    const float* ba_bupd1 = (const float*)d_in[16];
    const float* aa_Wsrc1 = (const float*)d_in[17];
    const float* aa_bsrc1 = (const float*)d_in[18];
    const float* aa_Wdst1 = (const float*)d_in[19];
    const float* aa_bdst1 = (const float*)d_in[20];
    const float* aa_Wupd1 = (const float*)d_in[21];
    const float* aa_bupd1 = (const float*)d_in[22];
    const float* Wsrc2 = (const float*)d_in[23];
    const float* bsrc2 = (const float*)d_in[24];
    const float* Wdst2 = (const float*)d_in[25];
    const float* bdst2 = (const float*)d_in[26];
    const float* Wupd2 = (const float*)d_in[27];
    const float* bupd2 = (const float*)d_in[28];
    const float* bn_g = (const float*)d_in[29];
    const float* bn_b = (const float*)d_in[30];
    float* out = (float*)d_out;

    float* aggr0 = symf(g_aggr0);
    float* aggr1 = symf(g_aggr1);
    float* aggr2 = symf(g_aggr2);
    float* hA = symf(g_hA);
    float* hB = symf(g_hB);
    float* preA = symf(g_preA);
    float* preB = symf(g_preB);
    float* xAt = symf(g_xAt);
    float* xBt = symf(g_xBt);
    int* icnt = symi(g_icnt);
    int* roff = symi(g_roff);
    int* csr = symi(g_csr);
    float* WA1 = symf(g_WA1);
    float* WB1 = symf(g_WB1);
    float* WA2 = symf(g_WA2);
    float* WB2 = symf(g_WB2);
    float* bA1 = symf(g_bA1);
    float* bB1 = symf(g_bB1);
    float* bA2 = symf(g_bA2);
    float* bB2 = symf(g_bB2);
    float* partA = symf(g_partA);
    float* partB = symf(g_partB);
    float* scA = symf(g_scA);
    float* shA = symf(g_shA);
    float* scB = symf(g_scB);
    float* shB = symf(g_shB);

    int* icnt_ab = icnt;          int* icnt_ba = icnt + NN;          int* icnt_aa = icnt + 2 * NN;
    int* roff_ab = roff;          int* roff_ba = roff + (NN + 1);    int* roff_aa = roff + 2 * (NN + 1);
    int* csr_ab = csr;            int* csr_ba = csr + NE;            int* csr_aa = csr + 2 * NE;

    const int EB = (NE + 255) / 256;
    const int G256 = (NN + 3) / 4;
    const int G128 = (NN + 7) / 8;
    dim3 ggrid(2, (NN + 127) / 128);

    // one-time resources
    static cudaStream_t sW = nullptr, sB = nullptr, sC = nullptr;
    static cudaEvent_t evFork, evZero, evW, evAb, evBa, evAa, evHA, evG0, evG1, evDone;
    static bool inited = false;
    if (!inited) {
        inited = true;
        cudaStreamCreateWithFlags(&sW, cudaStreamNonBlocking);
        cudaStreamCreateWithFlags(&sB, cudaStreamNonBlocking);
        cudaStreamCreateWithFlags(&sC, cudaStreamNonBlocking);
        cudaEventCreateWithFlags(&evFork, cudaEventDisableTiming);
        cudaEventCreateWithFlags(&evZero, cudaEventDisableTiming);
        cudaEventCreateWithFlags(&evW, cudaEventDisableTiming);
        cudaEventCreateWithFlags(&evAb, cudaEventDisableTiming);
        cudaEventCreateWithFlags(&evBa, cudaEventDisableTiming);
        cudaEventCreateWithFlags(&evAa, cudaEventDisableTiming);
        cudaEventCreateWithFlags(&evHA, cudaEventDisableTiming);
        cudaEventCreateWithFlags(&evG0, cudaEventDisableTiming);
        cudaEventCreateWithFlags(&evG1, cudaEventDisableTiming);
        cudaEventCreateWithFlags(&evDone, cudaEventDisableTiming);
        cudaFuncSetAttribute(gemm_tf32_kernel,
                             cudaFuncAttributeMaxDynamicSharedMemorySize, GEMM_SMEM);
    }

    // ---- descriptor packs (pointers rebuilt every call) ----
    WDescPack wp;
    {
        int t = 0; int i = 0;
        auto add = [&](const float* A1, const float* B1, const float* A2, const float* B2,
                       float* o, int ostride, int ocoff, int d, float scale) {
            wp.w[i] = {A1, B1, A2, B2, o, 512, d, ostride, ocoff, scale, t};
            t += 4 * (d >> 6); i++;
        };
        add(ba_Wupd1, ba_Wdst1, aa_Wupd1, aa_Wdst1, WA1, 640, 0, 256, 0.5f);
        add(ba_Wupd1 + 256, ba_Wsrc1, nullptr, nullptr, WA1, 640, 256, 128, 0.5f);
        add(aa_Wupd1 + 256, aa_Wsrc1, nullptr, nullptr, WA1, 640, 384, 256, 0.5f);
        add(ab_Wupd1, ab_Wdst1, nullptr, nullptr, WB1, 384, 0, 128, 1.0f);
        add(ab_Wupd1 + 256, ab_Wsrc1, nullptr, nullptr, WB1, 384, 128, 256, 1.0f);
        add(Wupd2 + 131072, Wdst2 + 65536, Wupd2 + 262144, Wdst2 + 131072, WA2, 768, 0, 256, 0.5f);
        add(Wupd2 + 131072 + 256, Wsrc2 + 65536, nullptr, nullptr, WA2, 768, 256, 256, 0.5f);
        add(Wupd2 + 262144 + 256, Wsrc2 + 131072, nullptr, nullptr, WA2, 768, 512, 256, 0.5f);
        add(Wupd2, Wdst2, nullptr, nullptr, WB2, 512, 0, 256, 1.0f);
        add(Wupd2 + 256, Wsrc2, nullptr, nullptr, WB2, 512, 256, 256, 1.0f);
        // total tiles t = 144
    }
    BDescPack bp;
    bp.b[0] = {ba_Wupd1, ba_bsrc1, ba_bdst1, ba_bupd1,
               aa_Wupd1, aa_bsrc1, aa_bdst1, aa_bupd1, bA1, 0.5f};
    bp.b[1] = {ab_Wupd1, ab_bsrc1, ab_bdst1, ab_bupd1,
               nullptr, nullptr, nullptr, nullptr, bB1, 1.0f};
    bp.b[2] = {Wupd2 + 131072, bsrc2 + 256, bdst2 + 256, bupd2 + 256,
               Wupd2 + 262144, bsrc2 + 512, bdst2 + 512, bupd2 + 512, bA2, 0.5f};
    bp.b[3] = {Wupd2, bsrc2, bdst2, bupd2,
               nullptr, nullptr, nullptr, nullptr, bB2, 1.0f};

    // ---- fork (every side stream MUST join capture via an event from the origin stream) ----
    cudaEventRecord(evFork, 0);               // capture fork point, before any origin work
    cudaStreamWaitEvent(sW, evFork, 0);       // sW joins capture here (no dependency on zeroing)

    zero_int_kernel<<<(3 * NN + 255) / 256, 256>>>(icnt, 3 * NN);
    cudaEventRecord(evZero, 0);
    cudaStreamWaitEvent(sB, evZero, 0);
    cudaStreamWaitEvent(sC, evZero, 0);

    // stream sW: input rounding + batched weight/bias combines
    round_kernel<<<G256, 256, 0, sW>>>(x_A, xAt, NN * 64);
    round_kernel<<<G128, 256, 0, sW>>>(x_B, xBt, NN * 32);
    combine_w_batched<<<144, 256, 0, sW>>>(wp);
    combine_b_batched<<<4, 256, 0, sW>>>(bp);
    cudaEventRecord(evW, sW);

    // stream sB: ba chain
    count_int_kernel<<<EB, 256, 0, sB>>>(e_ba + NE, icnt_ba, NE);
    scan_kernel<<<1, 1024, 0, sB>>>(icnt_ba, roff_ba);
    fill_kernel<<<EB, 256, 0, sB>>>(e_ba, e_ba + NE, roff_ba, icnt_ba, csr_ba, NE);
    gather128_kernel<<<G128, 256, 0, sB>>>(x_B, roff_ba, csr_ba, aggr1);
    cudaEventRecord(evBa, sB);

    // stream sC: aa chain
    count_int_kernel<<<EB, 256, 0, sC>>>(e_aa + NE, icnt_aa, NE);
    scan_kernel<<<1, 1024, 0, sC>>>(icnt_aa, roff_aa);
    fill_kernel<<<EB, 256, 0, sC>>>(e_aa, e_aa + NE, roff_aa, icnt_aa, csr_aa, NE);
    gather256_kernel<<<G256, 256, 0, sC>>>(x_A, roff_aa, csr_aa, aggr2);
    cudaEventRecord(evAa, sC);

    // default stream: ab chain
    count_int_kernel<<<EB, 256>>>(e_ab + NE, icnt_ab, NE);
    scan_kernel<<<1, 1024>>>(icnt_ab, roff_ab);
    fill_kernel<<<EB, 256>>>(e_ab, e_ab + NE, roff_ab, icnt_ab, csr_ab, NE);
    gather256_kernel<<<G256, 256>>>(x_A, roff_ab, csr_ab, aggr0);
    cudaEventRecord(evAb, 0);

    // ---- layer 1 GEMM A + BN (default stream), GEMM B + BN (sB) concurrently ----
    cudaStreamWaitEvent(0, evW, 0);
    cudaStreamWaitEvent(0, evBa, 0);
    cudaStreamWaitEvent(0, evAa, 0);
    gemm_tf32_kernel<<<ggrid, 256, GEMM_SMEM>>>(xAt, 256, aggr1, 128, aggr2, 256, WA1, bA1, preA, NN);
    stats_kernel<<<STATS_BLKS, 256>>>(preA, NN, partA);
    bn_finalize_kernel<<<1, 256>>>(partA, bn_g + 0, bn_b + 0, NN, scA, shA);
    bn_apply_kernel<<<G256, 256>>>(preA, scA, shA, hA, NN, 1);
    cudaEventRecord(evHA, 0);

    cudaStreamWaitEvent(sB, evAb, 0);
    cudaStreamWaitEvent(sB, evW, 0);
    gemm_tf32_kernel<<<ggrid, 256, GEMM_SMEM, sB>>>(xBt, 128, aggr0, 256, nullptr, 0, WB1, bB1, preB, NN);
    stats_kernel<<<STATS_BLKS, 256, 0, sB>>>(preB, NN, partB);
    bn_finalize_kernel<<<1, 256, 0, sB>>>(partB, bn_g + 256, bn_b + 256, NN, scB, shB);
    bn_apply_kernel<<<G256, 256, 0, sB>>>(preB, scB, shB, hB, NN, 1);
    gather256_kernel<<<G256, 256, 0, sB>>>(hB, roff_ba, csr_ba, aggr1);
    cudaEventRecord(evG1, sB);

    // stream sC: layer 2 ab gather (needs hA)
    cudaStreamWaitEvent(sC, evHA, 0);
    gather256_kernel<<<G256, 256, 0, sC>>>(hA, roff_ab, csr_ab, aggr0);
    cudaEventRecord(evG0, sC);

    // default stream: layer 2 aa gather
    gather256_kernel<<<G256, 256>>>(hA, roff_aa, csr_aa, aggr2);

    // ---- layer 2 GEMM A + BN (default), GEMM B + BN (sB) ----
    cudaStreamWaitEvent(0, evG1, 0);
    gemm_tf32_kernel<<<ggrid, 256, GEMM_SMEM>>>(hA, 256, aggr1, 256, aggr2, 256, WA2, bA2, preA, NN);
    stats_kernel<<<STATS_BLKS, 256>>>(preA, NN, partA);
    bn_finalize_kernel<<<1, 256>>>(partA, bn_g + 512, bn_b + 512, NN, scA, shA);
    bn_apply_kernel<<<G256, 256>>>(preA, scA, shA, out, NN, 0);

    cudaStreamWaitEvent(sB, evG0, 0);
    gemm_tf32_kernel<<<ggrid, 256, GEMM_SMEM, sB>>>(hB, 256, aggr0, 256, nullptr, 0, WB2, bB2, preB, NN);
    stats_kernel<<<STATS_BLKS, 256, 0, sB>>>(preB, NN, partB);
    bn_finalize_kernel<<<1, 256, 0, sB>>>(partB, bn_g + 768, bn_b + 768, NN, scB, shB);
    bn_apply_kernel<<<G256, 256, 0, sB>>>(preB, scB, shB, out + (size_t)NN * HD, NN, 0);
    cudaEventRecord(evDone, sB);

    cudaStreamWaitEvent(0, evDone, 0);
}